// round 2
// baseline (speedup 1.0000x reference)
#include <cuda_runtime.h>
#include <cuda_bf16.h>
#include <math.h>

// ---------------------------------------------------------------------------
// Problem dims
// ---------------------------------------------------------------------------
#define BATCH 8
#define LSEQ  4096          // 64*64
#define DMODEL 256
#define NHEAD 8
#define DHEAD 32
#define MROWS (BATCH*LSEQ)  // 32768
#define NUM_LAYERS 4

// ---------------------------------------------------------------------------
// Scratch (device globals -- no allocations allowed)
// ---------------------------------------------------------------------------
__device__ float g_x  [MROWS * DMODEL];   // activations [b,l,d]
__device__ float g_q  [MROWS * DMODEL];   // Q, later reused as "merged"
__device__ float g_k  [MROWS * DMODEL];   // K, later reused as h2
__device__ float g_v  [MROWS * DMODEL];   // V
__device__ float g_msg[MROWS * DMODEL];   // attention output
__device__ float g_cat[MROWS * 2*DMODEL]; // [x | LN1(merged)]
__device__ float g_h1 [MROWS * 2*DMODEL]; // relu(cat @ W1)
__device__ float g_kv  [BATCH * NHEAD * DHEAD * DHEAD];
__device__ float g_ksum[BATCH * NHEAD * DHEAD];

// ---------------------------------------------------------------------------
// Positional encoding value for (channel c, position l)  (l = y*64 + x)
// ---------------------------------------------------------------------------
__device__ __forceinline__ float pe_val(int c, int l) {
    int i = c >> 2;
    int m = c & 3;
    float pos = (m < 2) ? (float)((l & 63) + 1) : (float)((l >> 6) + 1);
    // div = exp(-(2*i) * ln(10000)/128)
    float dv = expf(-(float)(2 * i) * 0.07195578490697396f);
    float a = pos * dv;
    return (m & 1) ? cosf(a) : sinf(a);
}

// ---------------------------------------------------------------------------
// K0: feats [b,c,l] -> x [b,l,c]  with positional encoding added
// grid (128, 8, 8)  block (32, 8)
// ---------------------------------------------------------------------------
__global__ void add_pe_transpose(const float* __restrict__ feats) {
    __shared__ float t[32][33];
    int b  = blockIdx.z;
    int c0 = blockIdx.y * 32;
    int l0 = blockIdx.x * 32;
    int tx = threadIdx.x, ty = threadIdx.y;
    #pragma unroll
    for (int i = ty; i < 32; i += 8) {
        int c = c0 + i, l = l0 + tx;
        t[i][tx] = feats[((size_t)b * DMODEL + c) * LSEQ + l] + pe_val(c, l);
    }
    __syncthreads();
    #pragma unroll
    for (int i = ty; i < 32; i += 8) {
        int l = l0 + i, c = c0 + tx;
        g_x[((size_t)b * LSEQ + l) * DMODEL + c] = t[tx][i];
    }
}

// ---------------------------------------------------------------------------
// K-last: x [b,l,c] -> out [b,c,l]
// ---------------------------------------------------------------------------
__global__ void transpose_out(float* __restrict__ out) {
    __shared__ float t[32][33];
    int b  = blockIdx.z;
    int c0 = blockIdx.y * 32;
    int l0 = blockIdx.x * 32;
    int tx = threadIdx.x, ty = threadIdx.y;
    #pragma unroll
    for (int i = ty; i < 32; i += 8)
        t[i][tx] = g_x[((size_t)b * LSEQ + l0 + i) * DMODEL + c0 + tx];
    __syncthreads();
    #pragma unroll
    for (int i = ty; i < 32; i += 8)
        out[((size_t)b * DMODEL + c0 + i) * LSEQ + l0 + tx] = t[tx][i];
}

// ---------------------------------------------------------------------------
// SGEMM: C[M,N] = A[M,K] @ B[K,N], row-major, all dims divisible.
// BM=BN=128, BK=8, 256 threads, 8x8 per thread.
// EPI: 0 = none, 1 = elu+1, 2 = relu
// ---------------------------------------------------------------------------
template <int EPI>
__device__ __forceinline__ float epi_fn(float v) {
    if (EPI == 1) return v > 0.f ? v + 1.f : expf(v);
    if (EPI == 2) return v > 0.f ? v : 0.f;
    return v;
}

template <int EPI>
__global__ __launch_bounds__(256) void sgemm(
    const float* __restrict__ A, const float* __restrict__ B,
    float* __restrict__ C, int M, int N, int K)
{
    __shared__ __align__(16) float As[8][128];
    __shared__ __align__(16) float Bs[8][128];

    int tid = threadIdx.x;
    int bn = blockIdx.x, bm = blockIdx.y;

    const float* Ablk = A + (size_t)bm * 128 * K;
    const float* Bblk = B + (size_t)bn * 128;

    int arow = tid >> 1,  acol = (tid & 1) * 4;   // 128x8 A tile
    int brow = tid >> 5,  bcol = (tid & 31) * 4;  // 8x128 B tile
    int ty = tid >> 4, tx = tid & 15;

    float acc[8][8];
    #pragma unroll
    for (int i = 0; i < 8; i++)
        #pragma unroll
        for (int j = 0; j < 8; j++) acc[i][j] = 0.f;

    for (int k0 = 0; k0 < K; k0 += 8) {
        float4 av = *(const float4*)(Ablk + (size_t)arow * K + k0 + acol);
        float4 bv = *(const float4*)(Bblk + (size_t)(k0 + brow) * N + bcol);
        As[acol + 0][arow] = av.x;
        As[acol + 1][arow] = av.y;
        As[acol + 2][arow] = av.z;
        As[acol + 3][arow] = av.w;
        *(float4*)(&Bs[brow][bcol]) = bv;
        __syncthreads();

        #pragma unroll
        for (int k = 0; k < 8; k++) {
            float4 a0 = *(const float4*)(&As[k][ty * 8]);
            float4 a1 = *(const float4*)(&As[k][ty * 8 + 4]);
            float4 b0 = *(const float4*)(&Bs[k][tx * 8]);
            float4 b1 = *(const float4*)(&Bs[k][tx * 8 + 4]);
            float ar[8] = {a0.x, a0.y, a0.z, a0.w, a1.x, a1.y, a1.z, a1.w};
            float br[8] = {b0.x, b0.y, b0.z, b0.w, b1.x, b1.y, b1.z, b1.w};
            #pragma unroll
            for (int i = 0; i < 8; i++)
                #pragma unroll
                for (int j = 0; j < 8; j++)
                    acc[i][j] += ar[i] * br[j];
        }
        __syncthreads();
    }

    float* Cp = C + (size_t)(bm * 128) * N + bn * 128;
    #pragma unroll
    for (int i = 0; i < 8; i++) {
        #pragma unroll
        for (int j = 0; j < 8; j += 4) {
            float4 o;
            o.x = epi_fn<EPI>(acc[i][j + 0]);
            o.y = epi_fn<EPI>(acc[i][j + 1]);
            o.z = epi_fn<EPI>(acc[i][j + 2]);
            o.w = epi_fn<EPI>(acc[i][j + 3]);
            *(float4*)(Cp + (size_t)(ty * 8 + i) * N + tx * 8 + j) = o;
        }
    }
}

// ---------------------------------------------------------------------------
// KV reduce: per (n,h): KV[d,v] = sum_l K[l,d]*V[l,v];  Ksum[d] = sum_l K[l,d]
// grid 64 blocks (n*8+h), 256 threads
// ---------------------------------------------------------------------------
__global__ __launch_bounds__(256) void kv_reduce() {
    int n = blockIdx.x >> 3;
    int h = blockIdx.x & 7;
    const float* Kp = g_k + (size_t)n * LSEQ * DMODEL + h * DHEAD;
    const float* Vp = g_v + (size_t)n * LSEQ * DMODEL + h * DHEAD;

    __shared__ float sK[8][32];
    __shared__ float sV[8][32];

    int tid = threadIdx.x;
    int d0 = tid >> 3;            // 0..31
    int v0 = (tid & 7) * 4;       // 0,4,...,28
    float acc0 = 0.f, acc1 = 0.f, acc2 = 0.f, acc3 = 0.f;
    float ks = 0.f;
    int lr = tid >> 5, lc = tid & 31;

    for (int l0 = 0; l0 < LSEQ; l0 += 8) {
        sK[lr][lc] = Kp[(size_t)(l0 + lr) * DMODEL + lc];
        sV[lr][lc] = Vp[(size_t)(l0 + lr) * DMODEL + lc];
        __syncthreads();
        #pragma unroll
        for (int r = 0; r < 8; r++) {
            float kd = sK[r][d0];
            acc0 += kd * sV[r][v0 + 0];
            acc1 += kd * sV[r][v0 + 1];
            acc2 += kd * sV[r][v0 + 2];
            acc3 += kd * sV[r][v0 + 3];
            if ((tid & 7) == 0) ks += kd;
        }
        __syncthreads();
    }

    float* kvp = g_kv + (size_t)blockIdx.x * DHEAD * DHEAD + d0 * DHEAD + v0;
    kvp[0] = acc0; kvp[1] = acc1; kvp[2] = acc2; kvp[3] = acc3;
    if ((tid & 7) == 0) g_ksum[(size_t)blockIdx.x * DHEAD + d0] = ks;
}

// ---------------------------------------------------------------------------
// Attention apply: msg[l,h,v] = (sum_d Q[l,h,d]*KV[h,d,v]) / (Q.Ksum + eps)
// grid (32 l-tiles, 8 batch), 256 threads; 128 rows per block.
// ---------------------------------------------------------------------------
__global__ __launch_bounds__(256) void attn_apply() {
    int n  = blockIdx.y;
    int l0 = blockIdx.x * 128;
    __shared__ float sKV[NHEAD][DHEAD][DHEAD];   // 32 KB
    __shared__ float sKs[NHEAD][DHEAD];

    int tid = threadIdx.x;
    const float* kvp = g_kv + (size_t)n * NHEAD * DHEAD * DHEAD;
    for (int i = tid; i < NHEAD * DHEAD * DHEAD; i += 256)
        ((float*)sKV)[i] = kvp[i];
    for (int i = tid; i < NHEAD * DHEAD; i += 256)
        ((float*)sKs)[i] = g_ksum[(size_t)n * NHEAD * DHEAD + i];
    __syncthreads();

    #pragma unroll
    for (int p = 0; p < 4; p++) {
        int i  = p * 256 + tid;    // 0..1023
        int h  = i >> 7;           // warp-uniform
        int ll = i & 127;
        const float* qp = g_q + ((size_t)n * LSEQ + l0 + ll) * DMODEL + h * DHEAD;
        float q[32];
        #pragma unroll
        for (int d = 0; d < 32; d += 4) {
            float4 t = *(const float4*)(qp + d);
            q[d] = t.x; q[d + 1] = t.y; q[d + 2] = t.z; q[d + 3] = t.w;
        }
        float zdot = 0.f;
        #pragma unroll
        for (int d = 0; d < 32; d++) zdot += q[d] * sKs[h][d];
        float z = 1.f / (zdot + 1e-6f);

        float* mp = g_msg + ((size_t)n * LSEQ + l0 + ll) * DMODEL + h * DHEAD;
        #pragma unroll
        for (int v = 0; v < 32; v += 4) {
            float a0 = 0.f, a1 = 0.f, a2 = 0.f, a3 = 0.f;
            #pragma unroll
            for (int d = 0; d < 32; d++) {
                float qq = q[d];
                a0 += qq * sKV[h][d][v + 0];
                a1 += qq * sKV[h][d][v + 1];
                a2 += qq * sKV[h][d][v + 2];
                a3 += qq * sKV[h][d][v + 3];
            }
            float4 o = {a0 * z, a1 * z, a2 * z, a3 * z};
            *(float4*)(mp + v) = o;
        }
    }
}

// ---------------------------------------------------------------------------
// LayerNorm helpers: one warp per 256-wide row, 8 rows per block
// ---------------------------------------------------------------------------
__device__ __forceinline__ float warp_sum(float v) {
    #pragma unroll
    for (int o = 16; o > 0; o >>= 1) v += __shfl_xor_sync(0xffffffffu, v, o);
    return v;
}

// LN1: cat[:,0:256] = x, cat[:,256:512] = LN(merged)
__global__ __launch_bounds__(256) void ln1_cat(
    const float* __restrict__ inp, const float* __restrict__ gam,
    const float* __restrict__ bet)
{
    int row  = blockIdx.x * 8 + (threadIdx.x >> 5);
    int lane = threadIdx.x & 31;
    const float* ip = inp + (size_t)row * DMODEL;
    float v[8]; float s = 0.f;
    #pragma unroll
    for (int j = 0; j < 8; j++) { v[j] = ip[lane + 32 * j]; s += v[j]; }
    s = warp_sum(s);
    float mu = s * (1.f / 256.f);
    float s2 = 0.f;
    #pragma unroll
    for (int j = 0; j < 8; j++) { float d = v[j] - mu; s2 += d * d; }
    s2 = warp_sum(s2);
    float rs = rsqrtf(s2 * (1.f / 256.f) + 1e-5f);

    float* cp = g_cat + (size_t)row * 2 * DMODEL;
    const float* xp = g_x + (size_t)row * DMODEL;
    #pragma unroll
    for (int j = 0; j < 8; j++) {
        int c = lane + 32 * j;
        cp[c] = xp[c];
        cp[DMODEL + c] = (v[j] - mu) * rs * gam[c] + bet[c];
    }
}

// LN2 + residual: x += LN(h2)
__global__ __launch_bounds__(256) void ln2_res(
    const float* __restrict__ inp, const float* __restrict__ gam,
    const float* __restrict__ bet)
{
    int row  = blockIdx.x * 8 + (threadIdx.x >> 5);
    int lane = threadIdx.x & 31;
    const float* ip = inp + (size_t)row * DMODEL;
    float v[8]; float s = 0.f;
    #pragma unroll
    for (int j = 0; j < 8; j++) { v[j] = ip[lane + 32 * j]; s += v[j]; }
    s = warp_sum(s);
    float mu = s * (1.f / 256.f);
    float s2 = 0.f;
    #pragma unroll
    for (int j = 0; j < 8; j++) { float d = v[j] - mu; s2 += d * d; }
    s2 = warp_sum(s2);
    float rs = rsqrtf(s2 * (1.f / 256.f) + 1e-5f);

    float* xp = g_x + (size_t)row * DMODEL;
    #pragma unroll
    for (int j = 0; j < 8; j++) {
        int c = lane + 32 * j;
        xp[c] += (v[j] - mu) * rs * gam[c] + bet[c];
    }
}

// ---------------------------------------------------------------------------
// Host orchestration
// ---------------------------------------------------------------------------
extern "C" void kernel_launch(void* const* d_in, const int* in_sizes, int n_in,
                              void* d_out, int out_size)
{
    const float* feats  = (const float*)d_in[0];
    const float* Wq     = (const float*)d_in[1];
    const float* Wk     = (const float*)d_in[2];
    const float* Wv     = (const float*)d_in[3];
    const float* Wm     = (const float*)d_in[4];
    const float* W1     = (const float*)d_in[5];
    const float* W2     = (const float*)d_in[6];
    const float* ln1g   = (const float*)d_in[7];
    const float* ln1b   = (const float*)d_in[8];
    const float* ln2g   = (const float*)d_in[9];
    const float* ln2b   = (const float*)d_in[10];

    float *px, *pq, *pk, *pv, *pmsg, *pcat, *ph1;
    cudaGetSymbolAddress((void**)&px,   g_x);
    cudaGetSymbolAddress((void**)&pq,   g_q);
    cudaGetSymbolAddress((void**)&pk,   g_k);
    cudaGetSymbolAddress((void**)&pv,   g_v);
    cudaGetSymbolAddress((void**)&pmsg, g_msg);
    cudaGetSymbolAddress((void**)&pcat, g_cat);
    cudaGetSymbolAddress((void**)&ph1,  g_h1);

    dim3 tb(32, 8);
    add_pe_transpose<<<dim3(LSEQ / 32, DMODEL / 32, BATCH), tb>>>(feats);

    const int M = MROWS;
    dim3 blk(256);
    dim3 grid_d (DMODEL / 128, M / 128);       // N=256
    dim3 grid_2d(2 * DMODEL / 128, M / 128);   // N=512

    for (int i = 0; i < NUM_LAYERS; i++) {
        const float* wq = Wq + (size_t)i * DMODEL * DMODEL;
        const float* wk = Wk + (size_t)i * DMODEL * DMODEL;
        const float* wv = Wv + (size_t)i * DMODEL * DMODEL;
        const float* wm = Wm + (size_t)i * DMODEL * DMODEL;
        const float* w1 = W1 + (size_t)i * 2 * DMODEL * 2 * DMODEL;
        const float* w2 = W2 + (size_t)i * 2 * DMODEL * DMODEL;

        // Q = elu(x@Wq)+1, K = elu(x@Wk)+1, V = x@Wv (unscaled; /L and *L cancel)
        sgemm<1><<<grid_d, blk>>>(px, wq, pq, M, DMODEL, DMODEL);
        sgemm<1><<<grid_d, blk>>>(px, wk, pk, M, DMODEL, DMODEL);
        sgemm<0><<<grid_d, blk>>>(px, wv, pv, M, DMODEL, DMODEL);

        kv_reduce<<<BATCH * NHEAD, 256>>>();
        attn_apply<<<dim3(LSEQ / 128, BATCH), 256>>>();

        // merged = msg @ Wm  (reuse g_q)
        sgemm<0><<<grid_d, blk>>>(pmsg, wm, pq, M, DMODEL, DMODEL);

        // cat = [x | LN1(merged)]
        ln1_cat<<<M / 8, 256>>>(pq, ln1g + i * DMODEL, ln1b + i * DMODEL);

        // h1 = relu(cat @ W1);  h2 = h1 @ W2 (reuse g_k)
        sgemm<2><<<grid_2d, blk>>>(pcat, w1, ph1, M, 2 * DMODEL, 2 * DMODEL);
        sgemm<0><<<grid_d, blk>>>(ph1, w2, pk, M, DMODEL, 2 * DMODEL);

        // x += LN2(h2)
        ln2_res<<<M / 8, 256>>>(pk, ln2g + i * DMODEL, ln2b + i * DMODEL);
    }

    transpose_out<<<dim3(LSEQ / 32, DMODEL / 32, BATCH), tb>>>((float*)d_out);
}

// round 4
// speedup vs baseline: 1.8532x; 1.8532x over previous
#include <cuda_runtime.h>
#include <cuda_bf16.h>
#include <math.h>
#include <cstdint>

#define BATCH 8
#define LSEQ  4096
#define DMODEL 256
#define NHEAD 8
#define DHEAD 32
#define MROWS (BATCH*LSEQ)
#define NUM_LAYERS 4

// ---------------- helpers ----------------
__device__ __forceinline__ uint32_t smem_u32(const void* p) {
    uint32_t a;
    asm("{ .reg .u64 t; cvta.to.shared.u64 t, %1; cvt.u32.u64 %0, t; }" : "=r"(a) : "l"(p));
    return a;
}
__device__ __forceinline__ void cpa(uint32_t s, const void* g) {
    asm volatile("cp.async.cg.shared.global [%0], [%1], 16;" :: "r"(s), "l"(g));
}
__device__ __forceinline__ void cpa_commit() { asm volatile("cp.async.commit_group;" ::: "memory"); }
#define CPA_WAIT(n) asm volatile("cp.async.wait_group %0;" :: "n"(n) : "memory")
__device__ __forceinline__ void ldm_x4(uint32_t* r, uint32_t a) {
    asm volatile("ldmatrix.sync.aligned.m8n8.x4.shared.b16 {%0,%1,%2,%3}, [%4];"
        : "=r"(r[0]), "=r"(r[1]), "=r"(r[2]), "=r"(r[3]) : "r"(a));
}
#define MMA(c, a, b0v, b1v) \
    asm volatile("mma.sync.aligned.m16n8k16.row.col.f32.bf16.bf16.f32 " \
        "{%0,%1,%2,%3}, {%4,%5,%6,%7}, {%8,%9}, {%0,%1,%2,%3};" \
        : "+f"((c)[0]), "+f"((c)[1]), "+f"((c)[2]), "+f"((c)[3]) \
        : "r"((a)[0]), "r"((a)[1]), "r"((a)[2]), "r"((a)[3]), "r"(b0v), "r"(b1v))
__device__ __forceinline__ void split2(float v, __nv_bfloat16& h, __nv_bfloat16& l) {
    h = __float2bfloat16_rn(v);
    l = __float2bfloat16_rn(v - __bfloat162float(h));
}

// ---------------- scratch ----------------
__device__ float g_x[MROWS * DMODEL];
__device__ float g_q[MROWS * DMODEL];
__device__ float g_k[MROWS * DMODEL];
__device__ float g_v[MROWS * DMODEL];
__device__ float g_kv[BATCH * NHEAD * DHEAD * DHEAD];
__device__ float g_ksum[BATCH * NHEAD * DHEAD];
__device__ float g_kvp[BATCH * NHEAD * 8 * (DHEAD * DHEAD + DHEAD)];
__device__ __nv_bfloat16 g_xh[MROWS * DMODEL], g_xl[MROWS * DMODEL];
__device__ __nv_bfloat16 g_msgh[MROWS * DMODEL], g_msgl[MROWS * DMODEL];
__device__ __nv_bfloat16 g_cath[MROWS * 2 * DMODEL], g_catl[MROWS * 2 * DMODEL];
__device__ __nv_bfloat16 g_h1h[MROWS * 2 * DMODEL], g_h1l[MROWS * 2 * DMODEL];
__device__ __nv_bfloat16 g_wh[NUM_LAYERS * 10 * DMODEL * DMODEL];
__device__ __nv_bfloat16 g_wl[NUM_LAYERS * 10 * DMODEL * DMODEL];
#define WSZ_D (DMODEL * DMODEL)
#define WSZ_L (10 * WSZ_D)
#define OFF_Q 0
#define OFF_K (1 * WSZ_D)
#define OFF_V (2 * WSZ_D)
#define OFF_M (3 * WSZ_D)
#define OFF_1 (4 * WSZ_D)
#define OFF_2 (8 * WSZ_D)

// ---------------- PE + transposes ----------------
__device__ __forceinline__ float pe_val(int c, int l) {
    int i = c >> 2, m = c & 3;
    float pos = (m < 2) ? (float)((l & 63) + 1) : (float)((l >> 6) + 1);
    float dv = expf(-(float)(2 * i) * 0.07195578490697396f);
    float a = pos * dv;
    return (m & 1) ? cosf(a) : sinf(a);
}
__global__ void add_pe_transpose(const float* __restrict__ feats) {
    __shared__ float t[32][33];
    int b = blockIdx.z, c0 = blockIdx.y * 32, l0 = blockIdx.x * 32;
    int tx = threadIdx.x, ty = threadIdx.y;
    #pragma unroll
    for (int i = ty; i < 32; i += 8) {
        int c = c0 + i, l = l0 + tx;
        t[i][tx] = feats[((size_t)b * DMODEL + c) * LSEQ + l] + pe_val(c, l);
    }
    __syncthreads();
    #pragma unroll
    for (int i = ty; i < 32; i += 8) {
        int l = l0 + i, c = c0 + tx;
        float v = t[tx][i];
        size_t o = ((size_t)b * LSEQ + l) * DMODEL + c;
        g_x[o] = v;
        __nv_bfloat16 h, lo; split2(v, h, lo);
        g_xh[o] = h; g_xl[o] = lo;
    }
}
__global__ void transpose_out(float* __restrict__ out) {
    __shared__ float t[32][33];
    int b = blockIdx.z, c0 = blockIdx.y * 32, l0 = blockIdx.x * 32;
    int tx = threadIdx.x, ty = threadIdx.y;
    #pragma unroll
    for (int i = ty; i < 32; i += 8)
        t[i][tx] = g_x[((size_t)b * LSEQ + l0 + i) * DMODEL + c0 + tx];
    __syncthreads();
    #pragma unroll
    for (int i = ty; i < 32; i += 8)
        out[((size_t)b * DMODEL + c0 + i) * LSEQ + l0 + tx] = t[tx][i];
}

// W[K][N] fp32 -> [N][K] bf16 hi/lo (transpose + split)
__global__ void prep_weight(const float* __restrict__ W, __nv_bfloat16* __restrict__ Th,
                            __nv_bfloat16* __restrict__ Tl, int K, int N, int wstride, int ostride) {
    __shared__ float t[32][33];
    int L = blockIdx.z;
    const float* Wp = W + (size_t)L * wstride;
    int k0 = blockIdx.y * 32, n0 = blockIdx.x * 32;
    int tx = threadIdx.x, ty = threadIdx.y;
    #pragma unroll
    for (int i = ty; i < 32; i += 8)
        t[i][tx] = Wp[(size_t)(k0 + i) * N + n0 + tx];
    __syncthreads();
    #pragma unroll
    for (int i = ty; i < 32; i += 8) {
        float v = t[tx][i];
        size_t o = (size_t)L * ostride + (size_t)(n0 + i) * K + k0 + tx;
        __nv_bfloat16 h, l; split2(v, h, l);
        Th[o] = h; Tl[o] = l;
    }
}

// ---------------- mma.sync bf16 3-pass GEMM ----------------
// C[M,N] = A[M,K]@B^T, A split (Ah,Al) [M][K], B split (Bh,Bl) [N][K].
// CTA 128x128, BK=32, 3-stage cp.async. 8 warps (2m x 4n), warp tile 64x32.
// EPI: 0 fp32, 1 elu+1 fp32, 2 relu + bf16 split
#define BM 128
#define BN 128
#define BK 32
#define STG_BYTES 32768          // Ah 8K | Al 8K | Bh 8K | Bl 8K
#define NSTAGE 3
#define GSMEM (NSTAGE * STG_BYTES)

// in-tile byte offset for (row, slab s, half h) with conflict-free swizzle
__device__ __forceinline__ uint32_t tile_off(int row, int s, int h) {
    return (uint32_t)(s * 4096 + row * 32 + ((h ^ ((row >> 2) & 1)) * 16));
}

template <int EPI>
__global__ __launch_bounds__(256, 1) void mmagemm(
    const __nv_bfloat16* __restrict__ Ah, const __nv_bfloat16* __restrict__ Al,
    const __nv_bfloat16* __restrict__ Bh, const __nv_bfloat16* __restrict__ Bl,
    float* __restrict__ Cf, __nv_bfloat16* __restrict__ Ch,
    __nv_bfloat16* __restrict__ Cl, int Ndim, int Kdim)
{
    extern __shared__ char sraw[];
    const uint32_t sbase = smem_u32(sraw);

    const int tid = threadIdx.x;
    const int bm0 = blockIdx.y * BM, bn0 = blockIdx.x * BN;
    const int lane = tid & 31, warp = tid >> 5;
    const int wm = warp >> 2, wn = warp & 3;

    // ---- loader mapping: each thread fills one (row, slab) of each tile
    const int lm = tid & 127;          // row within tile
    const int ls = tid >> 7;           // slab 0/1
    const uint32_t lo0 = tile_off(lm, ls, 0);
    const uint32_t lo1 = lo0 ^ 16;

    // ---- ldmatrix address bases (within-tile, slab 0, add s*4096 at use)
    uint32_t adrA[4], adrB[2];
    {
        int kA = lane >> 4;
        #pragma unroll
        for (int mt = 0; mt < 4; mt++) {
            int row = wm * 64 + mt * 16 + (lane & 15);
            adrA[mt] = sbase + tile_off(row, 0, kA);
        }
        int kB = (lane >> 3) & 1;
        #pragma unroll
        for (int g = 0; g < 2; g++) {
            int row = wn * 32 + g * 16 + ((lane >> 4) & 1) * 8 + (lane & 7);
            adrB[g] = sbase + 16384 + tile_off(row, 0, kB);
        }
    }

    float acc[4][4][4];
    #pragma unroll
    for (int i = 0; i < 4; i++)
        #pragma unroll
        for (int j = 0; j < 4; j++)
            #pragma unroll
            for (int e = 0; e < 4; e++) acc[i][j][e] = 0.f;

    const int nk = Kdim / BK;

    // prologue: stages 0..NSTAGE-2
    #pragma unroll
    for (int st = 0; st < NSTAGE - 1; st++) {
        uint32_t sb = sbase + st * STG_BYTES;
        int kblk = st * BK;
        size_t gA = (size_t)(bm0 + lm) * Kdim + kblk + ls * 16;
        size_t gB = (size_t)(bn0 + lm) * Kdim + kblk + ls * 16;
        cpa(sb + lo0, Ah + gA);          cpa(sb + lo1, Ah + gA + 8);
        cpa(sb + 8192 + lo0, Al + gA);   cpa(sb + 8192 + lo1, Al + gA + 8);
        cpa(sb + 16384 + lo0, Bh + gB);  cpa(sb + 16384 + lo1, Bh + gB + 8);
        cpa(sb + 24576 + lo0, Bl + gB);  cpa(sb + 24576 + lo1, Bl + gB + 8);
        cpa_commit();
    }

    for (int c = 0; c < nk; c++) {
        CPA_WAIT(NSTAGE - 2);
        __syncthreads();
        uint32_t soff = (uint32_t)(c % NSTAGE) * STG_BYTES;

        #pragma unroll
        for (int s = 0; s < 2; s++) {
            uint32_t o = soff + s * 4096;
            uint32_t ah[4][4], al[4][4], bh[2][4], bl[2][4];
            #pragma unroll
            for (int mt = 0; mt < 4; mt++) {
                ldm_x4(ah[mt], adrA[mt] + o);
                ldm_x4(al[mt], adrA[mt] + 8192 + o);
            }
            #pragma unroll
            for (int g = 0; g < 2; g++) {
                ldm_x4(bh[g], adrB[g] + o);
                ldm_x4(bl[g], adrB[g] + 8192 + o);
            }
            #pragma unroll
            for (int mt = 0; mt < 4; mt++)
                #pragma unroll
                for (int nt = 0; nt < 4; nt++)
                    MMA(acc[mt][nt], ah[mt], bh[nt >> 1][(nt & 1) * 2], bh[nt >> 1][(nt & 1) * 2 + 1]);
            #pragma unroll
            for (int mt = 0; mt < 4; mt++)
                #pragma unroll
                for (int nt = 0; nt < 4; nt++)
                    MMA(acc[mt][nt], ah[mt], bl[nt >> 1][(nt & 1) * 2], bl[nt >> 1][(nt & 1) * 2 + 1]);
            #pragma unroll
            for (int mt = 0; mt < 4; mt++)
                #pragma unroll
                for (int nt = 0; nt < 4; nt++)
                    MMA(acc[mt][nt], al[mt], bh[nt >> 1][(nt & 1) * 2], bh[nt >> 1][(nt & 1) * 2 + 1]);
        }
        __syncthreads();

        int cn = c + NSTAGE - 1;
        if (cn < nk) {
            uint32_t sb = sbase + (uint32_t)(cn % NSTAGE) * STG_BYTES;
            int kblk = cn * BK;
            size_t gA = (size_t)(bm0 + lm) * Kdim + kblk + ls * 16;
            size_t gB = (size_t)(bn0 + lm) * Kdim + kblk + ls * 16;
            cpa(sb + lo0, Ah + gA);          cpa(sb + lo1, Ah + gA + 8);
            cpa(sb + 8192 + lo0, Al + gA);   cpa(sb + 8192 + lo1, Al + gA + 8);
            cpa(sb + 16384 + lo0, Bh + gB);  cpa(sb + 16384 + lo1, Bh + gB + 8);
            cpa(sb + 24576 + lo0, Bl + gB);  cpa(sb + 24576 + lo1, Bl + gB + 8);
        }
        cpa_commit();
    }

    // ---- epilogue
    #pragma unroll
    for (int mt = 0; mt < 4; mt++) {
        #pragma unroll
        for (int nt = 0; nt < 4; nt++) {
            int row = bm0 + wm * 64 + mt * 16 + (lane >> 2);
            int col = bn0 + wn * 32 + nt * 8 + (lane & 3) * 2;
            float* a = acc[mt][nt];
            #pragma unroll
            for (int half = 0; half < 2; half++) {
                int r = row + half * 8;
                float v0 = a[half * 2], v1 = a[half * 2 + 1];
                size_t o = (size_t)r * Ndim + col;
                if (EPI == 0) {
                    float2 t = {v0, v1};
                    *(float2*)(Cf + o) = t;
                } else if (EPI == 1) {
                    float2 t = {v0 > 0.f ? v0 + 1.f : expf(v0),
                                v1 > 0.f ? v1 + 1.f : expf(v1)};
                    *(float2*)(Cf + o) = t;
                } else {
                    v0 = v0 > 0.f ? v0 : 0.f;
                    v1 = v1 > 0.f ? v1 : 0.f;
                    __nv_bfloat16 h0, l0, h1, l1;
                    split2(v0, h0, l0); split2(v1, h1, l1);
                    __nv_bfloat162 ph; ph.x = h0; ph.y = h1;
                    __nv_bfloat162 pl; pl.x = l0; pl.y = l1;
                    *(__nv_bfloat162*)(Ch + o) = ph;
                    *(__nv_bfloat162*)(Cl + o) = pl;
                }
            }
        }
    }
}

// ---------------- KV reduce (two-phase) ----------------
__global__ __launch_bounds__(256) void kv_reduce1() {
    int blk = blockIdx.x;
    int sl = blk & 7, nh = blk >> 3;
    int n = nh >> 3, h = nh & 7;
    const float* Kp = g_k + (size_t)n * LSEQ * DMODEL + h * DHEAD;
    const float* Vp = g_v + (size_t)n * LSEQ * DMODEL + h * DHEAD;
    __shared__ float sK[8][32], sV[8][32];
    int tid = threadIdx.x;
    int d0 = tid >> 3, v0 = (tid & 7) * 4;
    float a0 = 0, a1 = 0, a2 = 0, a3 = 0, ks = 0;
    int lr = tid >> 5, lc = tid & 31;
    int lbeg = sl * 512, lend = lbeg + 512;
    for (int l0 = lbeg; l0 < lend; l0 += 8) {
        sK[lr][lc] = Kp[(size_t)(l0 + lr) * DMODEL + lc];
        sV[lr][lc] = Vp[(size_t)(l0 + lr) * DMODEL + lc];
        __syncthreads();
        #pragma unroll
        for (int r = 0; r < 8; r++) {
            float kd = sK[r][d0];
            a0 += kd * sV[r][v0 + 0];
            a1 += kd * sV[r][v0 + 1];
            a2 += kd * sV[r][v0 + 2];
            a3 += kd * sV[r][v0 + 3];
            if ((tid & 7) == 0) ks += kd;
        }
        __syncthreads();
    }
    float* p = g_kvp + (size_t)blk * (DHEAD * DHEAD + DHEAD);
    float* kv = p + d0 * DHEAD + v0;
    kv[0] = a0; kv[1] = a1; kv[2] = a2; kv[3] = a3;
    if ((tid & 7) == 0) p[DHEAD * DHEAD + d0] = ks;
}
__global__ __launch_bounds__(256) void kv_reduce2() {
    int nh = blockIdx.x, tid = threadIdx.x;
    const float* base = g_kvp + (size_t)nh * 8 * (DHEAD * DHEAD + DHEAD);
    #pragma unroll
    for (int ii = 0; ii < 4; ii++) {
        int i = ii * 256 + tid;
        float s = 0;
        #pragma unroll
        for (int p = 0; p < 8; p++) s += base[p * (DHEAD * DHEAD + DHEAD) + i];
        g_kv[(size_t)nh * DHEAD * DHEAD + i] = s;
    }
    if (tid < DHEAD) {
        float s = 0;
        #pragma unroll
        for (int p = 0; p < 8; p++) s += base[p * (DHEAD * DHEAD + DHEAD) + DHEAD * DHEAD + tid];
        g_ksum[(size_t)nh * DHEAD + tid] = s;
    }
}

// ---------------- attention apply ----------------
__global__ __launch_bounds__(256) void attn_apply() {
    int n = blockIdx.y, l0 = blockIdx.x * 128;
    __shared__ float sKV[NHEAD][DHEAD][DHEAD];
    __shared__ float sKs[NHEAD][DHEAD];
    int tid = threadIdx.x;
    const float* kvp = g_kv + (size_t)n * NHEAD * DHEAD * DHEAD;
    for (int i = tid; i < NHEAD * DHEAD * DHEAD; i += 256) ((float*)sKV)[i] = kvp[i];
    for (int i = tid; i < NHEAD * DHEAD; i += 256) ((float*)sKs)[i] = g_ksum[(size_t)n * NHEAD * DHEAD + i];
    __syncthreads();
    #pragma unroll
    for (int p = 0; p < 4; p++) {
        int i = p * 256 + tid;
        int h = i >> 7, ll = i & 127;
        size_t rowo = ((size_t)n * LSEQ + l0 + ll) * DMODEL + h * DHEAD;
        const float* qp = g_q + rowo;
        float q[32];
        #pragma unroll
        for (int d = 0; d < 32; d += 4) {
            float4 t = *(const float4*)(qp + d);
            q[d] = t.x; q[d + 1] = t.y; q[d + 2] = t.z; q[d + 3] = t.w;
        }
        float zdot = 0.f;
        #pragma unroll
        for (int d = 0; d < 32; d++) zdot += q[d] * sKs[h][d];
        float z = 1.f / (zdot + 1e-6f);
        #pragma unroll
        for (int v = 0; v < 32; v += 2) {
            float b0 = 0.f, b1 = 0.f;
            #pragma unroll
            for (int d = 0; d < 32; d++) {
                float qq = q[d];
                b0 += qq * sKV[h][d][v];
                b1 += qq * sKV[h][d][v + 1];
            }
            b0 *= z; b1 *= z;
            __nv_bfloat16 h0, l0b, h1, l1b;
            split2(b0, h0, l0b); split2(b1, h1, l1b);
            __nv_bfloat162 ph; ph.x = h0; ph.y = h1;
            __nv_bfloat162 pl; pl.x = l0b; pl.y = l1b;
            *(__nv_bfloat162*)(g_msgh + rowo + v) = ph;
            *(__nv_bfloat162*)(g_msgl + rowo + v) = pl;
        }
    }
}

// ---------------- LayerNorms ----------------
__device__ __forceinline__ float warp_sum(float v) {
    #pragma unroll
    for (int o = 16; o > 0; o >>= 1) v += __shfl_xor_sync(0xffffffffu, v, o);
    return v;
}
__global__ __launch_bounds__(256) void ln1_cat(
    const float* __restrict__ inp, const float* __restrict__ gam, const float* __restrict__ bet)
{
    int row = blockIdx.x * 8 + (threadIdx.x >> 5);
    int lane = threadIdx.x & 31;
    const float* ip = inp + (size_t)row * DMODEL;
    float v[8]; float s = 0.f;
    #pragma unroll
    for (int j = 0; j < 8; j++) { v[j] = ip[lane + 32 * j]; s += v[j]; }
    s = warp_sum(s);
    float mu = s * (1.f / 256.f), s2 = 0.f;
    #pragma unroll
    for (int j = 0; j < 8; j++) { float d = v[j] - mu; s2 += d * d; }
    s2 = warp_sum(s2);
    float rs = rsqrtf(s2 * (1.f / 256.f) + 1e-5f);
    size_t co = (size_t)row * 2 * DMODEL;
    const float* xp = g_x + (size_t)row * DMODEL;
    #pragma unroll
    for (int j = 0; j < 8; j++) {
        int c = lane + 32 * j;
        __nv_bfloat16 h, l;
        split2(xp[c], h, l);
        g_cath[co + c] = h; g_catl[co + c] = l;
        float lnv = (v[j] - mu) * rs * gam[c] + bet[c];
        split2(lnv, h, l);
        g_cath[co + DMODEL + c] = h; g_catl[co + DMODEL + c] = l;
    }
}
__global__ __launch_bounds__(256) void ln2_res(
    const float* __restrict__ inp, const float* __restrict__ gam, const float* __restrict__ bet)
{
    int row = blockIdx.x * 8 + (threadIdx.x >> 5);
    int lane = threadIdx.x & 31;
    const float* ip = inp + (size_t)row * DMODEL;
    float v[8]; float s = 0.f;
    #pragma unroll
    for (int j = 0; j < 8; j++) { v[j] = ip[lane + 32 * j]; s += v[j]; }
    s = warp_sum(s);
    float mu = s * (1.f / 256.f), s2 = 0.f;
    #pragma unroll
    for (int j = 0; j < 8; j++) { float d = v[j] - mu; s2 += d * d; }
    s2 = warp_sum(s2);
    float rs = rsqrtf(s2 * (1.f / 256.f) + 1e-5f);
    float* xp = g_x + (size_t)row * DMODEL;
    size_t xo = (size_t)row * DMODEL;
    #pragma unroll
    for (int j = 0; j < 8; j++) {
        int c = lane + 32 * j;
        float nx = xp[c] + (v[j] - mu) * rs * gam[c] + bet[c];
        xp[c] = nx;
        __nv_bfloat16 h, l; split2(nx, h, l);
        g_xh[xo + c] = h; g_xl[xo + c] = l;
    }
}

// ---------------- host ----------------
extern "C" void kernel_launch(void* const* d_in, const int* in_sizes, int n_in,
                              void* d_out, int out_size)
{
    const float* feats = (const float*)d_in[0];
    const float* Wq = (const float*)d_in[1];
    const float* Wk = (const float*)d_in[2];
    const float* Wv = (const float*)d_in[3];
    const float* Wm = (const float*)d_in[4];
    const float* W1 = (const float*)d_in[5];
    const float* W2 = (const float*)d_in[6];
    const float* ln1g = (const float*)d_in[7];
    const float* ln1b = (const float*)d_in[8];
    const float* ln2g = (const float*)d_in[9];
    const float* ln2b = (const float*)d_in[10];

    cudaFuncSetAttribute(mmagemm<0>, cudaFuncAttributeMaxDynamicSharedMemorySize, GSMEM);
    cudaFuncSetAttribute(mmagemm<1>, cudaFuncAttributeMaxDynamicSharedMemorySize, GSMEM);
    cudaFuncSetAttribute(mmagemm<2>, cudaFuncAttributeMaxDynamicSharedMemorySize, GSMEM);

    float *px, *pq, *pk, *pv;
    __nv_bfloat16 *pxh, *pxl, *pmh, *pml, *pch, *pcl, *p1h, *p1l, *pwh, *pwl;
    cudaGetSymbolAddress((void**)&px, g_x);
    cudaGetSymbolAddress((void**)&pq, g_q);
    cudaGetSymbolAddress((void**)&pk, g_k);
    cudaGetSymbolAddress((void**)&pv, g_v);
    cudaGetSymbolAddress((void**)&pxh, g_xh);
    cudaGetSymbolAddress((void**)&pxl, g_xl);
    cudaGetSymbolAddress((void**)&pmh, g_msgh);
    cudaGetSymbolAddress((void**)&pml, g_msgl);
    cudaGetSymbolAddress((void**)&pch, g_cath);
    cudaGetSymbolAddress((void**)&pcl, g_catl);
    cudaGetSymbolAddress((void**)&p1h, g_h1h);
    cudaGetSymbolAddress((void**)&p1l, g_h1l);
    cudaGetSymbolAddress((void**)&pwh, g_wh);
    cudaGetSymbolAddress((void**)&pwl, g_wl);

    dim3 tb(32, 8);
    prep_weight<<<dim3(8, 8, NUM_LAYERS), tb>>>(Wq, pwh + OFF_Q, pwl + OFF_Q, DMODEL, DMODEL, WSZ_D, WSZ_L);
    prep_weight<<<dim3(8, 8, NUM_LAYERS), tb>>>(Wk, pwh + OFF_K, pwl + OFF_K, DMODEL, DMODEL, WSZ_D, WSZ_L);
    prep_weight<<<dim3(8, 8, NUM_LAYERS), tb>>>(Wv, pwh + OFF_V, pwl + OFF_V, DMODEL, DMODEL, WSZ_D, WSZ_L);
    prep_weight<<<dim3(8, 8, NUM_LAYERS), tb>>>(Wm, pwh + OFF_M, pwl + OFF_M, DMODEL, DMODEL, WSZ_D, WSZ_L);
    prep_weight<<<dim3(16, 16, NUM_LAYERS), tb>>>(W1, pwh + OFF_1, pwl + OFF_1, 2 * DMODEL, 2 * DMODEL, 4 * WSZ_D, WSZ_L);
    prep_weight<<<dim3(8, 16, NUM_LAYERS), tb>>>(W2, pwh + OFF_2, pwl + OFF_2, 2 * DMODEL, DMODEL, 2 * WSZ_D, WSZ_L);

    add_pe_transpose<<<dim3(LSEQ / 32, DMODEL / 32, BATCH), tb>>>(feats);

    dim3 blk(256);
    dim3 grid_d(DMODEL / BN, MROWS / BM);       // (2, 256)
    dim3 grid_2d(2 * DMODEL / BN, MROWS / BM);  // (4, 256)

    for (int i = 0; i < NUM_LAYERS; i++) {
        size_t wo = (size_t)i * WSZ_L;
        mmagemm<1><<<grid_d, blk, GSMEM>>>(pxh, pxl, pwh + wo + OFF_Q, pwl + wo + OFF_Q, pq, 0, 0, DMODEL, DMODEL);
        mmagemm<1><<<grid_d, blk, GSMEM>>>(pxh, pxl, pwh + wo + OFF_K, pwl + wo + OFF_K, pk, 0, 0, DMODEL, DMODEL);
        mmagemm<0><<<grid_d, blk, GSMEM>>>(pxh, pxl, pwh + wo + OFF_V, pwl + wo + OFF_V, pv, 0, 0, DMODEL, DMODEL);

        kv_reduce1<<<BATCH * NHEAD * 8, 256>>>();
        kv_reduce2<<<BATCH * NHEAD, 256>>>();
        attn_apply<<<dim3(LSEQ / 128, BATCH), 256>>>();

        mmagemm<0><<<grid_d, blk, GSMEM>>>(pmh, pml, pwh + wo + OFF_M, pwl + wo + OFF_M, pq, 0, 0, DMODEL, DMODEL);
        ln1_cat<<<MROWS / 8, 256>>>(pq, ln1g + i * DMODEL, ln1b + i * DMODEL);

        mmagemm<2><<<grid_2d, blk, GSMEM>>>(pch, pcl, pwh + wo + OFF_1, pwl + wo + OFF_1, 0, p1h, p1l, 2 * DMODEL, 2 * DMODEL);
        mmagemm<0><<<grid_d, blk, GSMEM>>>(p1h, p1l, pwh + wo + OFF_2, pwl + wo + OFF_2, pk, 0, 0, DMODEL, 2 * DMODEL);

        ln2_res<<<MROWS / 8, 256>>>(pk, ln2g + i * DMODEL, ln2b + i * DMODEL);
    }

    transpose_out<<<dim3(LSEQ / 32, DMODEL / 32, BATCH), tb>>>((float*)d_out);
}

// round 5
// speedup vs baseline: 2.9772x; 1.6065x over previous
#include <cuda_runtime.h>
#include <cuda_bf16.h>
#include <math.h>
#include <cstdint>

#define BATCH 8
#define LSEQ  4096
#define DMODEL 256
#define NHEAD 8
#define DHEAD 32
#define MROWS (BATCH*LSEQ)
#define NUM_LAYERS 4
#define QKVN (3*DMODEL)   // 768

// ---------------- helpers ----------------
__device__ __forceinline__ uint32_t smem_u32(const void* p) {
    uint32_t a;
    asm("{ .reg .u64 t; cvta.to.shared.u64 t, %1; cvt.u32.u64 %0, t; }" : "=r"(a) : "l"(p));
    return a;
}
__device__ __forceinline__ void cpa(uint32_t s, const void* g) {
    asm volatile("cp.async.cg.shared.global [%0], [%1], 16;" :: "r"(s), "l"(g));
}
__device__ __forceinline__ void cpa_commit() { asm volatile("cp.async.commit_group;" ::: "memory"); }
#define CPA_WAIT(n) asm volatile("cp.async.wait_group %0;" :: "n"(n) : "memory")
__device__ __forceinline__ void ldm_x4(uint32_t* r, uint32_t a) {
    asm volatile("ldmatrix.sync.aligned.m8n8.x4.shared.b16 {%0,%1,%2,%3}, [%4];"
        : "=r"(r[0]), "=r"(r[1]), "=r"(r[2]), "=r"(r[3]) : "r"(a));
}
#define MMA(c, a, b0v, b1v) \
    asm volatile("mma.sync.aligned.m16n8k16.row.col.f32.bf16.bf16.f32 " \
        "{%0,%1,%2,%3}, {%4,%5,%6,%7}, {%8,%9}, {%0,%1,%2,%3};" \
        : "+f"((c)[0]), "+f"((c)[1]), "+f"((c)[2]), "+f"((c)[3]) \
        : "r"((a)[0]), "r"((a)[1]), "r"((a)[2]), "r"((a)[3]), "r"(b0v), "r"(b1v))
__device__ __forceinline__ void split2(float v, __nv_bfloat16& h, __nv_bfloat16& l) {
    h = __float2bfloat16_rn(v);
    l = __float2bfloat16_rn(v - __bfloat162float(h));
}

// ---------------- scratch ----------------
__device__ float g_x[MROWS * DMODEL];
__device__ float g_qkv[MROWS * QKVN];
__device__ float g_tmp[MROWS * DMODEL];
__device__ float g_kv[BATCH * NHEAD * DHEAD * DHEAD];
__device__ float g_ksum[BATCH * NHEAD * DHEAD];
__device__ float g_kvp[BATCH * NHEAD * 8 * (DHEAD * DHEAD + DHEAD)];
__device__ __nv_bfloat16 g_xh[MROWS * DMODEL], g_xl[MROWS * DMODEL];
__device__ __nv_bfloat16 g_msgh[MROWS * DMODEL], g_msgl[MROWS * DMODEL];
__device__ __nv_bfloat16 g_cath[MROWS * 2 * DMODEL], g_catl[MROWS * 2 * DMODEL];
__device__ __nv_bfloat16 g_h1h[MROWS * 2 * DMODEL], g_h1l[MROWS * 2 * DMODEL];
__device__ __nv_bfloat16 g_wh[NUM_LAYERS * 10 * DMODEL * DMODEL];
__device__ __nv_bfloat16 g_wl[NUM_LAYERS * 10 * DMODEL * DMODEL];
#define WSZ_D (DMODEL * DMODEL)
#define WSZ_L (10 * WSZ_D)
#define OFF_Q 0
#define OFF_K (1 * WSZ_D)
#define OFF_V (2 * WSZ_D)
#define OFF_M (3 * WSZ_D)
#define OFF_1 (4 * WSZ_D)
#define OFF_2 (8 * WSZ_D)

// ---------------- PE + transposes ----------------
__device__ __forceinline__ float pe_val(int c, int l) {
    int i = c >> 2, m = c & 3;
    float pos = (m < 2) ? (float)((l & 63) + 1) : (float)((l >> 6) + 1);
    float dv = expf(-(float)(2 * i) * 0.07195578490697396f);
    float a = pos * dv;
    return (m & 1) ? cosf(a) : sinf(a);
}
__global__ void add_pe_transpose(const float* __restrict__ feats) {
    __shared__ float t[32][33];
    int b = blockIdx.z, c0 = blockIdx.y * 32, l0 = blockIdx.x * 32;
    int tx = threadIdx.x, ty = threadIdx.y;
    #pragma unroll
    for (int i = ty; i < 32; i += 8) {
        int c = c0 + i, l = l0 + tx;
        t[i][tx] = feats[((size_t)b * DMODEL + c) * LSEQ + l] + pe_val(c, l);
    }
    __syncthreads();
    #pragma unroll
    for (int i = ty; i < 32; i += 8) {
        int l = l0 + i, c = c0 + tx;
        float v = t[tx][i];
        size_t o = ((size_t)b * LSEQ + l) * DMODEL + c;
        g_x[o] = v;
        __nv_bfloat16 h, lo; split2(v, h, lo);
        g_xh[o] = h; g_xl[o] = lo;
    }
}
__global__ void transpose_out(float* __restrict__ out) {
    __shared__ float t[32][33];
    int b = blockIdx.z, c0 = blockIdx.y * 32, l0 = blockIdx.x * 32;
    int tx = threadIdx.x, ty = threadIdx.y;
    #pragma unroll
    for (int i = ty; i < 32; i += 8)
        t[i][tx] = g_x[((size_t)b * LSEQ + l0 + i) * DMODEL + c0 + tx];
    __syncthreads();
    #pragma unroll
    for (int i = ty; i < 32; i += 8)
        out[((size_t)b * DMODEL + c0 + i) * LSEQ + l0 + tx] = t[tx][i];
}

// W[K][N] fp32 -> [N][K] bf16 hi/lo (transpose + split)
__global__ void prep_weight(const float* __restrict__ W, __nv_bfloat16* __restrict__ Th,
                            __nv_bfloat16* __restrict__ Tl, int K, int N, int wstride, int ostride) {
    __shared__ float t[32][33];
    int L = blockIdx.z;
    const float* Wp = W + (size_t)L * wstride;
    int k0 = blockIdx.y * 32, n0 = blockIdx.x * 32;
    int tx = threadIdx.x, ty = threadIdx.y;
    #pragma unroll
    for (int i = ty; i < 32; i += 8)
        t[i][tx] = Wp[(size_t)(k0 + i) * N + n0 + tx];
    __syncthreads();
    #pragma unroll
    for (int i = ty; i < 32; i += 8) {
        float v = t[tx][i];
        size_t o = (size_t)L * ostride + (size_t)(n0 + i) * K + k0 + tx;
        __nv_bfloat16 h, l; split2(v, h, l);
        Th[o] = h; Tl[o] = l;
    }
}

// ---------------- mma.sync bf16 3-pass GEMM ----------------
// C = A @ B^T. A split (Ah,Al) [M][K], B split (Bh,Bl) [N][K], bf16 row-major.
// CTA 128x128, BK=64, 3-stage cp.async ring, ONE barrier per chunk.
// 8 warps (2m x 4n), warp tile 64x32.
// EPI: 0 fp32, 1 elu+1 fp32, 2 relu + bf16 split, 3 qkv (elu+1 if col<512)
#define BM 128
#define BN 128
#define BK 64
#define STG_BYTES 65536          // Ah16K | Al16K | Bh16K | Bl16K
#define NSTAGE 3
#define GSMEM (NSTAGE * STG_BYTES)

template <int EPI>
__global__ __launch_bounds__(256, 1) void mmagemm(
    const __nv_bfloat16* __restrict__ Ah, const __nv_bfloat16* __restrict__ Al,
    const __nv_bfloat16* __restrict__ Bh, const __nv_bfloat16* __restrict__ Bl,
    float* __restrict__ Cf, __nv_bfloat16* __restrict__ Ch,
    __nv_bfloat16* __restrict__ Cl, int Ndim, int Kdim)
{
    extern __shared__ char sraw[];
    const uint32_t sbase = smem_u32(sraw);

    const int tid = threadIdx.x;
    const int bm0 = blockIdx.y * BM, bn0 = blockIdx.x * BN;
    const int lane = tid & 31, warp = tid >> 5;
    const int wm = warp >> 2, wn = warp & 3;

    // loader mapping: one 16B chunk per (tid, i): tiles are [128 rows][64 bf16], SW128
    const int lrow = tid >> 3;            // base row (stride 32 via i)
    const int lc16 = tid & 7;             // 16B col
    // ldmatrix frag bases
    uint32_t aRB[4]; int aR3[4];
    const int khA = lane >> 4;
    #pragma unroll
    for (int mt = 0; mt < 4; mt++) {
        int row = wm * 64 + mt * 16 + (lane & 15);
        aRB[mt] = sbase + row * 128;
        aR3[mt] = row & 7;
    }
    uint32_t bRB[2]; int bR3[2];
    const int khB = (lane >> 3) & 1;
    #pragma unroll
    for (int g = 0; g < 2; g++) {
        int row = wn * 32 + g * 16 + ((lane >> 4) & 1) * 8 + (lane & 7);
        bRB[g] = sbase + 32768 + row * 128;
        bR3[g] = row & 7;
    }

    float acc[4][4][4];
    #pragma unroll
    for (int i = 0; i < 4; i++)
        #pragma unroll
        for (int j = 0; j < 4; j++)
            #pragma unroll
            for (int e = 0; e < 4; e++) acc[i][j][e] = 0.f;

    const int nk = Kdim / BK;

    // stage loader
    auto load_stage = [&](int st, int kblk) {
        uint32_t sb = sbase + (uint32_t)st * STG_BYTES;
        #pragma unroll
        for (int i = 0; i < 4; i++) {
            int row = lrow + i * 32;
            uint32_t so = (uint32_t)(row * 128 + ((lc16 ^ (row & 7)) << 4));
            size_t gA = (size_t)(bm0 + row) * Kdim + kblk + lc16 * 8;
            size_t gB = (size_t)(bn0 + row) * Kdim + kblk + lc16 * 8;
            cpa(sb + so, Ah + gA);
            cpa(sb + 16384 + so, Al + gA);
            cpa(sb + 32768 + so, Bh + gB);
            cpa(sb + 49152 + so, Bl + gB);
        }
        cpa_commit();
    };

    load_stage(0, 0);
    load_stage(1, BK);

    for (int c = 0; c < nk; c++) {
        CPA_WAIT(NSTAGE - 2);
        __syncthreads();
        if (c + 2 < nk) load_stage((c + 2) % NSTAGE, (c + 2) * BK);
        else cpa_commit();

        uint32_t soff = (uint32_t)(c % NSTAGE) * STG_BYTES;
        #pragma unroll
        for (int s = 0; s < 4; s++) {       // four k16 slabs in BK=64
            uint32_t ah[4][4], al[4][4], bh[2][4], bl[2][4];
            #pragma unroll
            for (int mt = 0; mt < 4; mt++) {
                uint32_t a = aRB[mt] + soff + (uint32_t)(((s * 2 + khA) ^ aR3[mt]) << 4);
                ldm_x4(ah[mt], a);
                ldm_x4(al[mt], a + 16384);
            }
            #pragma unroll
            for (int g = 0; g < 2; g++) {
                uint32_t a = bRB[g] + soff + (uint32_t)(((s * 2 + khB) ^ bR3[g]) << 4);
                ldm_x4(bh[g], a);
                ldm_x4(bl[g], a + 16384);
            }
            #pragma unroll
            for (int mt = 0; mt < 4; mt++)
                #pragma unroll
                for (int nt = 0; nt < 4; nt++)
                    MMA(acc[mt][nt], ah[mt], bh[nt >> 1][(nt & 1) * 2], bh[nt >> 1][(nt & 1) * 2 + 1]);
            #pragma unroll
            for (int mt = 0; mt < 4; mt++)
                #pragma unroll
                for (int nt = 0; nt < 4; nt++)
                    MMA(acc[mt][nt], ah[mt], bl[nt >> 1][(nt & 1) * 2], bl[nt >> 1][(nt & 1) * 2 + 1]);
            #pragma unroll
            for (int mt = 0; mt < 4; mt++)
                #pragma unroll
                for (int nt = 0; nt < 4; nt++)
                    MMA(acc[mt][nt], al[mt], bh[nt >> 1][(nt & 1) * 2], bh[nt >> 1][(nt & 1) * 2 + 1]);
        }
    }

    // epilogue
    const bool qkv_act = (EPI == 3) && (bn0 < 2 * DMODEL);
    #pragma unroll
    for (int mt = 0; mt < 4; mt++) {
        #pragma unroll
        for (int nt = 0; nt < 4; nt++) {
            int row = bm0 + wm * 64 + mt * 16 + (lane >> 2);
            int col = bn0 + wn * 32 + nt * 8 + (lane & 3) * 2;
            float* a = acc[mt][nt];
            #pragma unroll
            for (int half = 0; half < 2; half++) {
                int r = row + half * 8;
                float v0 = a[half * 2], v1 = a[half * 2 + 1];
                size_t o = (size_t)r * Ndim + col;
                if (EPI == 0) {
                    float2 t = {v0, v1};
                    *(float2*)(Cf + o) = t;
                } else if (EPI == 1) {
                    float2 t = {v0 > 0.f ? v0 + 1.f : expf(v0),
                                v1 > 0.f ? v1 + 1.f : expf(v1)};
                    *(float2*)(Cf + o) = t;
                } else if (EPI == 3) {
                    float2 t;
                    if (qkv_act) {
                        t.x = v0 > 0.f ? v0 + 1.f : expf(v0);
                        t.y = v1 > 0.f ? v1 + 1.f : expf(v1);
                    } else { t.x = v0; t.y = v1; }
                    *(float2*)(Cf + o) = t;
                } else {
                    v0 = v0 > 0.f ? v0 : 0.f;
                    v1 = v1 > 0.f ? v1 : 0.f;
                    __nv_bfloat16 h0, l0, h1, l1;
                    split2(v0, h0, l0); split2(v1, h1, l1);
                    __nv_bfloat162 ph; ph.x = h0; ph.y = h1;
                    __nv_bfloat162 pl; pl.x = l0; pl.y = l1;
                    *(__nv_bfloat162*)(Ch + o) = ph;
                    *(__nv_bfloat162*)(Cl + o) = pl;
                }
            }
        }
    }
}

// ---------------- KV reduce (two-phase, 32-row tiles) ----------------
__global__ __launch_bounds__(256) void kv_reduce1() {
    int blk = blockIdx.x;
    int sl = blk & 7, nh = blk >> 3;
    int n = nh >> 3, h = nh & 7;
    const float* Kp = g_qkv + (size_t)n * LSEQ * QKVN + DMODEL + h * DHEAD;
    const float* Vp = Kp + DMODEL;
    __shared__ float sK[32][32], sV[32][32];
    int tid = threadIdx.x;
    int d0 = tid >> 3, v0 = (tid & 7) * 4;
    int lrow = tid >> 3, lcol = (tid & 7) * 4;
    float a0 = 0, a1 = 0, a2 = 0, a3 = 0, ks = 0;
    int lbeg = sl * 512, lend = lbeg + 512;
    for (int l0 = lbeg; l0 < lend; l0 += 32) {
        size_t ro = (size_t)(l0 + lrow) * QKVN + lcol;
        *(float4*)&sK[lrow][lcol] = *(const float4*)(Kp + ro);
        *(float4*)&sV[lrow][lcol] = *(const float4*)(Vp + ro);
        __syncthreads();
        #pragma unroll
        for (int r = 0; r < 32; r++) {
            float kd = sK[r][d0];
            a0 += kd * sV[r][v0 + 0];
            a1 += kd * sV[r][v0 + 1];
            a2 += kd * sV[r][v0 + 2];
            a3 += kd * sV[r][v0 + 3];
            if ((tid & 7) == 0) ks += kd;
        }
        __syncthreads();
    }
    float* p = g_kvp + (size_t)blk * (DHEAD * DHEAD + DHEAD);
    float* kv = p + d0 * DHEAD + v0;
    kv[0] = a0; kv[1] = a1; kv[2] = a2; kv[3] = a3;
    if ((tid & 7) == 0) p[DHEAD * DHEAD + d0] = ks;
}
__global__ __launch_bounds__(256) void kv_reduce2() {
    int nh = blockIdx.x, tid = threadIdx.x;
    const float* base = g_kvp + (size_t)nh * 8 * (DHEAD * DHEAD + DHEAD);
    #pragma unroll
    for (int ii = 0; ii < 4; ii++) {
        int i = ii * 256 + tid;
        float s = 0;
        #pragma unroll
        for (int p = 0; p < 8; p++) s += base[p * (DHEAD * DHEAD + DHEAD) + i];
        g_kv[(size_t)nh * DHEAD * DHEAD + i] = s;
    }
    if (tid < DHEAD) {
        float s = 0;
        #pragma unroll
        for (int p = 0; p < 8; p++) s += base[p * (DHEAD * DHEAD + DHEAD) + DHEAD * DHEAD + tid];
        g_ksum[(size_t)nh * DHEAD + tid] = s;
    }
}

// ---------------- attention apply ----------------
__global__ __launch_bounds__(256) void attn_apply() {
    int n = blockIdx.y, l0 = blockIdx.x * 128;
    __shared__ float sKV[NHEAD][DHEAD][DHEAD];
    __shared__ float sKs[NHEAD][DHEAD];
    int tid = threadIdx.x;
    const float* kvp = g_kv + (size_t)n * NHEAD * DHEAD * DHEAD;
    for (int i = tid; i < NHEAD * DHEAD * DHEAD; i += 256) ((float*)sKV)[i] = kvp[i];
    for (int i = tid; i < NHEAD * DHEAD; i += 256) ((float*)sKs)[i] = g_ksum[(size_t)n * NHEAD * DHEAD + i];
    __syncthreads();
    #pragma unroll
    for (int p = 0; p < 4; p++) {
        int i = p * 256 + tid;
        int h = i >> 7, ll = i & 127;
        const float* qp = g_qkv + ((size_t)n * LSEQ + l0 + ll) * QKVN + h * DHEAD;
        size_t rowo = ((size_t)n * LSEQ + l0 + ll) * DMODEL + h * DHEAD;
        float q[32];
        #pragma unroll
        for (int d = 0; d < 32; d += 4) {
            float4 t = *(const float4*)(qp + d);
            q[d] = t.x; q[d + 1] = t.y; q[d + 2] = t.z; q[d + 3] = t.w;
        }
        float zdot = 0.f;
        #pragma unroll
        for (int d = 0; d < 32; d++) zdot += q[d] * sKs[h][d];
        float z = 1.f / (zdot + 1e-6f);
        #pragma unroll
        for (int v = 0; v < 32; v += 2) {
            float b0 = 0.f, b1 = 0.f;
            #pragma unroll
            for (int d = 0; d < 32; d++) {
                float qq = q[d];
                b0 += qq * sKV[h][d][v];
                b1 += qq * sKV[h][d][v + 1];
            }
            b0 *= z; b1 *= z;
            __nv_bfloat16 h0, l0b, h1, l1b;
            split2(b0, h0, l0b); split2(b1, h1, l1b);
            __nv_bfloat162 ph; ph.x = h0; ph.y = h1;
            __nv_bfloat162 pl; pl.x = l0b; pl.y = l1b;
            *(__nv_bfloat162*)(g_msgh + rowo + v) = ph;
            *(__nv_bfloat162*)(g_msgl + rowo + v) = pl;
        }
    }
}

// ---------------- LayerNorms ----------------
__device__ __forceinline__ float warp_sum(float v) {
    #pragma unroll
    for (int o = 16; o > 0; o >>= 1) v += __shfl_xor_sync(0xffffffffu, v, o);
    return v;
}
__global__ __launch_bounds__(256) void ln1_cat(
    const float* __restrict__ inp, const float* __restrict__ gam, const float* __restrict__ bet)
{
    int row = blockIdx.x * 8 + (threadIdx.x >> 5);
    int lane = threadIdx.x & 31;
    const float* ip = inp + (size_t)row * DMODEL;
    float v[8]; float s = 0.f;
    #pragma unroll
    for (int j = 0; j < 8; j++) { v[j] = ip[lane + 32 * j]; s += v[j]; }
    s = warp_sum(s);
    float mu = s * (1.f / 256.f), s2 = 0.f;
    #pragma unroll
    for (int j = 0; j < 8; j++) { float d = v[j] - mu; s2 += d * d; }
    s2 = warp_sum(s2);
    float rs = rsqrtf(s2 * (1.f / 256.f) + 1e-5f);
    size_t co = (size_t)row * 2 * DMODEL;
    const float* xp = g_x + (size_t)row * DMODEL;
    #pragma unroll
    for (int j = 0; j < 8; j++) {
        int c = lane + 32 * j;
        __nv_bfloat16 h, l;
        split2(xp[c], h, l);
        g_cath[co + c] = h; g_catl[co + c] = l;
        float lnv = (v[j] - mu) * rs * gam[c] + bet[c];
        split2(lnv, h, l);
        g_cath[co + DMODEL + c] = h; g_catl[co + DMODEL + c] = l;
    }
}
__global__ __launch_bounds__(256) void ln2_res(
    const float* __restrict__ inp, const float* __restrict__ gam, const float* __restrict__ bet)
{
    int row = blockIdx.x * 8 + (threadIdx.x >> 5);
    int lane = threadIdx.x & 31;
    const float* ip = inp + (size_t)row * DMODEL;
    float v[8]; float s = 0.f;
    #pragma unroll
    for (int j = 0; j < 8; j++) { v[j] = ip[lane + 32 * j]; s += v[j]; }
    s = warp_sum(s);
    float mu = s * (1.f / 256.f), s2 = 0.f;
    #pragma unroll
    for (int j = 0; j < 8; j++) { float d = v[j] - mu; s2 += d * d; }
    s2 = warp_sum(s2);
    float rs = rsqrtf(s2 * (1.f / 256.f) + 1e-5f);
    float* xp = g_x + (size_t)row * DMODEL;
    size_t xo = (size_t)row * DMODEL;
    #pragma unroll
    for (int j = 0; j < 8; j++) {
        int c = lane + 32 * j;
        float nx = xp[c] + (v[j] - mu) * rs * gam[c] + bet[c];
        xp[c] = nx;
        __nv_bfloat16 h, l; split2(nx, h, l);
        g_xh[xo + c] = h; g_xl[xo + c] = l;
    }
}

// ---------------- host ----------------
extern "C" void kernel_launch(void* const* d_in, const int* in_sizes, int n_in,
                              void* d_out, int out_size)
{
    const float* feats = (const float*)d_in[0];
    const float* Wq = (const float*)d_in[1];
    const float* Wk = (const float*)d_in[2];
    const float* Wv = (const float*)d_in[3];
    const float* Wm = (const float*)d_in[4];
    const float* W1 = (const float*)d_in[5];
    const float* W2 = (const float*)d_in[6];
    const float* ln1g = (const float*)d_in[7];
    const float* ln1b = (const float*)d_in[8];
    const float* ln2g = (const float*)d_in[9];
    const float* ln2b = (const float*)d_in[10];

    cudaFuncSetAttribute(mmagemm<0>, cudaFuncAttributeMaxDynamicSharedMemorySize, GSMEM);
    cudaFuncSetAttribute(mmagemm<2>, cudaFuncAttributeMaxDynamicSharedMemorySize, GSMEM);
    cudaFuncSetAttribute(mmagemm<3>, cudaFuncAttributeMaxDynamicSharedMemorySize, GSMEM);

    float *px, *pqkv, *ptmp;
    __nv_bfloat16 *pxh, *pxl, *pmh, *pml, *pch, *pcl, *p1h, *p1l, *pwh, *pwl;
    cudaGetSymbolAddress((void**)&px, g_x);
    cudaGetSymbolAddress((void**)&pqkv, g_qkv);
    cudaGetSymbolAddress((void**)&ptmp, g_tmp);
    cudaGetSymbolAddress((void**)&pxh, g_xh);
    cudaGetSymbolAddress((void**)&pxl, g_xl);
    cudaGetSymbolAddress((void**)&pmh, g_msgh);
    cudaGetSymbolAddress((void**)&pml, g_msgl);
    cudaGetSymbolAddress((void**)&pch, g_cath);
    cudaGetSymbolAddress((void**)&pcl, g_catl);
    cudaGetSymbolAddress((void**)&p1h, g_h1h);
    cudaGetSymbolAddress((void**)&p1l, g_h1l);
    cudaGetSymbolAddress((void**)&pwh, g_wh);
    cudaGetSymbolAddress((void**)&pwl, g_wl);

    dim3 tb(32, 8);
    prep_weight<<<dim3(8, 8, NUM_LAYERS), tb>>>(Wq, pwh + OFF_Q, pwl + OFF_Q, DMODEL, DMODEL, WSZ_D, WSZ_L);
    prep_weight<<<dim3(8, 8, NUM_LAYERS), tb>>>(Wk, pwh + OFF_K, pwl + OFF_K, DMODEL, DMODEL, WSZ_D, WSZ_L);
    prep_weight<<<dim3(8, 8, NUM_LAYERS), tb>>>(Wv, pwh + OFF_V, pwl + OFF_V, DMODEL, DMODEL, WSZ_D, WSZ_L);
    prep_weight<<<dim3(8, 8, NUM_LAYERS), tb>>>(Wm, pwh + OFF_M, pwl + OFF_M, DMODEL, DMODEL, WSZ_D, WSZ_L);
    prep_weight<<<dim3(16, 16, NUM_LAYERS), tb>>>(W1, pwh + OFF_1, pwl + OFF_1, 2 * DMODEL, 2 * DMODEL, 4 * WSZ_D, WSZ_L);
    prep_weight<<<dim3(8, 16, NUM_LAYERS), tb>>>(W2, pwh + OFF_2, pwl + OFF_2, 2 * DMODEL, DMODEL, 2 * WSZ_D, WSZ_L);

    add_pe_transpose<<<dim3(LSEQ / 32, DMODEL / 32, BATCH), tb>>>(feats);

    dim3 blk(256);
    dim3 grid_qkv(QKVN / BN, MROWS / BM);       // (6, 256)
    dim3 grid_d(DMODEL / BN, MROWS / BM);       // (2, 256)
    dim3 grid_2d(2 * DMODEL / BN, MROWS / BM);  // (4, 256)

    for (int i = 0; i < NUM_LAYERS; i++) {
        size_t wo = (size_t)i * WSZ_L;
        // fused QKV: [elu(x@Wq)+1 | elu(x@Wk)+1 | x@Wv] -> g_qkv [M][768]
        mmagemm<3><<<grid_qkv, blk, GSMEM>>>(pxh, pxl, pwh + wo + OFF_Q, pwl + wo + OFF_Q, pqkv, 0, 0, QKVN, DMODEL);

        kv_reduce1<<<BATCH * NHEAD * 8, 256>>>();
        kv_reduce2<<<BATCH * NHEAD, 256>>>();
        attn_apply<<<dim3(LSEQ / 128, BATCH), 256>>>();

        mmagemm<0><<<grid_d, blk, GSMEM>>>(pmh, pml, pwh + wo + OFF_M, pwl + wo + OFF_M, ptmp, 0, 0, DMODEL, DMODEL);
        ln1_cat<<<MROWS / 8, 256>>>(ptmp, ln1g + i * DMODEL, ln1b + i * DMODEL);

        mmagemm<2><<<grid_2d, blk, GSMEM>>>(pch, pcl, pwh + wo + OFF_1, pwl + wo + OFF_1, 0, p1h, p1l, 2 * DMODEL, 2 * DMODEL);
        mmagemm<0><<<grid_d, blk, GSMEM>>>(p1h, p1l, pwh + wo + OFF_2, pwl + wo + OFF_2, ptmp, 0, 0, DMODEL, 2 * DMODEL);

        ln2_res<<<MROWS / 8, 256>>>(ptmp, ln2g + i * DMODEL, ln2b + i * DMODEL);
    }

    transpose_out<<<dim3(LSEQ / 32, DMODEL / 32, BATCH), tb>>>((float*)d_out);
}

// round 6
// speedup vs baseline: 3.0422x; 1.0218x over previous
#include <cuda_runtime.h>
#include <cuda_bf16.h>
#include <math.h>
#include <cstdint>

#define BATCH 8
#define LSEQ  4096
#define DMODEL 256
#define NHEAD 8
#define DHEAD 32
#define MROWS (BATCH*LSEQ)
#define NUM_LAYERS 4
#define QKVN (3*DMODEL)   // 768

// ---------------- helpers ----------------
__device__ __forceinline__ uint32_t smem_u32(const void* p) {
    uint32_t a;
    asm("{ .reg .u64 t; cvta.to.shared.u64 t, %1; cvt.u32.u64 %0, t; }" : "=r"(a) : "l"(p));
    return a;
}
__device__ __forceinline__ void cpa(uint32_t s, const void* g) {
    asm volatile("cp.async.cg.shared.global [%0], [%1], 16;" :: "r"(s), "l"(g));
}
__device__ __forceinline__ void cpa_commit() { asm volatile("cp.async.commit_group;" ::: "memory"); }
#define CPA_WAIT(n) asm volatile("cp.async.wait_group %0;" :: "n"(n) : "memory")
__device__ __forceinline__ void ldm_x4(uint32_t* r, uint32_t a) {
    asm volatile("ldmatrix.sync.aligned.m8n8.x4.shared.b16 {%0,%1,%2,%3}, [%4];"
        : "=r"(r[0]), "=r"(r[1]), "=r"(r[2]), "=r"(r[3]) : "r"(a));
}
#define MMA(c, a, b0v, b1v) \
    asm volatile("mma.sync.aligned.m16n8k16.row.col.f32.bf16.bf16.f32 " \
        "{%0,%1,%2,%3}, {%4,%5,%6,%7}, {%8,%9}, {%0,%1,%2,%3};" \
        : "+f"((c)[0]), "+f"((c)[1]), "+f"((c)[2]), "+f"((c)[3]) \
        : "r"((a)[0]), "r"((a)[1]), "r"((a)[2]), "r"((a)[3]), "r"(b0v), "r"(b1v))
__device__ __forceinline__ void split2(float v, __nv_bfloat16& h, __nv_bfloat16& l) {
    h = __float2bfloat16_rn(v);
    l = __float2bfloat16_rn(v - __bfloat162float(h));
}

// ---------------- scratch ----------------
__device__ float g_x[MROWS * DMODEL];
__device__ float g_qkv[MROWS * QKVN];
__device__ float g_tmp[MROWS * DMODEL];
__device__ float g_kv[BATCH * NHEAD * DHEAD * DHEAD];
__device__ float g_ksum[BATCH * NHEAD * DHEAD];
__device__ float g_kvp[BATCH * NHEAD * 8 * (DHEAD * DHEAD + DHEAD)];
__device__ __nv_bfloat16 g_xh[MROWS * DMODEL], g_xl[MROWS * DMODEL];
__device__ __nv_bfloat16 g_msgh[MROWS * DMODEL], g_msgl[MROWS * DMODEL];
__device__ __nv_bfloat16 g_lnh[MROWS * DMODEL], g_lnl[MROWS * DMODEL];
__device__ __nv_bfloat16 g_h1h[MROWS * 2 * DMODEL], g_h1l[MROWS * 2 * DMODEL];
__device__ __nv_bfloat16 g_wh[NUM_LAYERS * 10 * DMODEL * DMODEL];
__device__ __nv_bfloat16 g_wl[NUM_LAYERS * 10 * DMODEL * DMODEL];
#define WSZ_D (DMODEL * DMODEL)
#define WSZ_L (10 * WSZ_D)
#define OFF_Q 0
#define OFF_K (1 * WSZ_D)
#define OFF_V (2 * WSZ_D)
#define OFF_M (3 * WSZ_D)
#define OFF_1 (4 * WSZ_D)
#define OFF_2 (8 * WSZ_D)

// ---------------- PE + transposes ----------------
__device__ __forceinline__ float pe_val(int c, int l) {
    int i = c >> 2, m = c & 3;
    float pos = (m < 2) ? (float)((l & 63) + 1) : (float)((l >> 6) + 1);
    float dv = expf(-(float)(2 * i) * 0.07195578490697396f);
    float a = pos * dv;
    return (m & 1) ? cosf(a) : sinf(a);
}
__global__ void add_pe_transpose(const float* __restrict__ feats) {
    __shared__ float t[32][33];
    int b = blockIdx.z, c0 = blockIdx.y * 32, l0 = blockIdx.x * 32;
    int tx = threadIdx.x, ty = threadIdx.y;
    #pragma unroll
    for (int i = ty; i < 32; i += 8) {
        int c = c0 + i, l = l0 + tx;
        t[i][tx] = feats[((size_t)b * DMODEL + c) * LSEQ + l] + pe_val(c, l);
    }
    __syncthreads();
    #pragma unroll
    for (int i = ty; i < 32; i += 8) {
        int l = l0 + i, c = c0 + tx;
        float v = t[tx][i];
        size_t o = ((size_t)b * LSEQ + l) * DMODEL + c;
        g_x[o] = v;
        __nv_bfloat16 h, lo; split2(v, h, lo);
        g_xh[o] = h; g_xl[o] = lo;
    }
}
__global__ void transpose_out(float* __restrict__ out) {
    __shared__ float t[32][33];
    int b = blockIdx.z, c0 = blockIdx.y * 32, l0 = blockIdx.x * 32;
    int tx = threadIdx.x, ty = threadIdx.y;
    #pragma unroll
    for (int i = ty; i < 32; i += 8)
        t[i][tx] = g_x[((size_t)b * LSEQ + l0 + i) * DMODEL + c0 + tx];
    __syncthreads();
    #pragma unroll
    for (int i = ty; i < 32; i += 8)
        out[((size_t)b * DMODEL + c0 + i) * LSEQ + l0 + tx] = t[tx][i];
}

// W[K][N] fp32 -> [N][K] bf16 hi/lo (transpose + split)
__global__ void prep_weight(const float* __restrict__ W, __nv_bfloat16* __restrict__ Th,
                            __nv_bfloat16* __restrict__ Tl, int K, int N, int wstride, int ostride) {
    __shared__ float t[32][33];
    int L = blockIdx.z;
    const float* Wp = W + (size_t)L * wstride;
    int k0 = blockIdx.y * 32, n0 = blockIdx.x * 32;
    int tx = threadIdx.x, ty = threadIdx.y;
    #pragma unroll
    for (int i = ty; i < 32; i += 8)
        t[i][tx] = Wp[(size_t)(k0 + i) * N + n0 + tx];
    __syncthreads();
    #pragma unroll
    for (int i = ty; i < 32; i += 8) {
        float v = t[tx][i];
        size_t o = (size_t)L * ostride + (size_t)(n0 + i) * K + k0 + tx;
        __nv_bfloat16 h, l; split2(v, h, l);
        Th[o] = h; Tl[o] = l;
    }
}

// ---------------- mma.sync bf16 3-pass GEMM ----------------
// C = A @ B^T, Markidis split. CTA 128x128, BK=64, 3-stage cp.async ring,
// one barrier per chunk, register double-buffered fragments.
// DUALA: A columns [0,256) from (Ah,Al), [256,512) from (Ah2,Al2), both stride 256.
// EPI: 0 fp32, 2 relu + bf16 split, 3 qkv (elu+1 if col<512)
#define BM 128
#define BN 128
#define BK 64
#define STG_BYTES 65536
#define NSTAGE 3
#define GSMEM (NSTAGE * STG_BYTES)

template <int EPI, bool DUALA>
__global__ __launch_bounds__(256, 1) void mmagemm(
    const __nv_bfloat16* __restrict__ Ah, const __nv_bfloat16* __restrict__ Al,
    const __nv_bfloat16* __restrict__ Ah2, const __nv_bfloat16* __restrict__ Al2,
    const __nv_bfloat16* __restrict__ Bh, const __nv_bfloat16* __restrict__ Bl,
    float* __restrict__ Cf, __nv_bfloat16* __restrict__ Ch,
    __nv_bfloat16* __restrict__ Cl, int Ndim, int Kdim)
{
    extern __shared__ char sraw[];
    const uint32_t sbase = smem_u32(sraw);

    const int tid = threadIdx.x;
    const int bm0 = blockIdx.y * BM, bn0 = blockIdx.x * BN;
    const int lane = tid & 31, warp = tid >> 5;
    const int wm = warp >> 2, wn = warp & 3;

    const int lrow = tid >> 3;
    const int lc16 = tid & 7;

    uint32_t aRB[4]; int aR3[4];
    const int khA = lane >> 4;
    #pragma unroll
    for (int mt = 0; mt < 4; mt++) {
        int row = wm * 64 + mt * 16 + (lane & 15);
        aRB[mt] = sbase + row * 128;
        aR3[mt] = row & 7;
    }
    uint32_t bRB[2]; int bR3[2];
    const int khB = (lane >> 3) & 1;
    #pragma unroll
    for (int g = 0; g < 2; g++) {
        int row = wn * 32 + g * 16 + ((lane >> 4) & 1) * 8 + (lane & 7);
        bRB[g] = sbase + 32768 + row * 128;
        bR3[g] = row & 7;
    }

    float acc[4][4][4];
    #pragma unroll
    for (int i = 0; i < 4; i++)
        #pragma unroll
        for (int j = 0; j < 4; j++)
            #pragma unroll
            for (int e = 0; e < 4; e++) acc[i][j][e] = 0.f;

    const int nk = Kdim / BK;
    const int astrS = DUALA ? DMODEL : Kdim;

    auto load_stage = [&](int st, int kblk) {
        uint32_t sb = sbase + (uint32_t)st * STG_BYTES;
        const __nv_bfloat16 *pAh, *pAl;
        int acol, astr;
        if (DUALA && kblk >= DMODEL) {
            pAh = Ah2; pAl = Al2; acol = kblk - DMODEL; astr = DMODEL;
        } else {
            pAh = Ah; pAl = Al; acol = kblk; astr = astrS;
        }
        #pragma unroll
        for (int i = 0; i < 4; i++) {
            int row = lrow + i * 32;
            uint32_t so = (uint32_t)(row * 128 + ((lc16 ^ (row & 7)) << 4));
            size_t gA = (size_t)(bm0 + row) * astr + acol + lc16 * 8;
            size_t gB = (size_t)(bn0 + row) * Kdim + kblk + lc16 * 8;
            cpa(sb + so, pAh + gA);
            cpa(sb + 16384 + so, pAl + gA);
            cpa(sb + 32768 + so, Bh + gB);
            cpa(sb + 49152 + so, Bl + gB);
        }
        cpa_commit();
    };

    load_stage(0, 0);
    load_stage(1, BK);

    uint32_t ah[2][4][4], al[2][4][4], bh[2][2][4], bl[2][2][4];

    for (int c = 0; c < nk; c++) {
        CPA_WAIT(NSTAGE - 2);
        __syncthreads();
        if (c + 2 < nk) load_stage((c + 2) % NSTAGE, (c + 2) * BK);
        else cpa_commit();

        uint32_t soff = (uint32_t)(c % NSTAGE) * STG_BYTES;

        // frag load for slab 0 into buffer 0
        #pragma unroll
        for (int mt = 0; mt < 4; mt++) {
            uint32_t a = aRB[mt] + soff + (uint32_t)((khA ^ aR3[mt]) << 4);
            ldm_x4(ah[0][mt], a);
            ldm_x4(al[0][mt], a + 16384);
        }
        #pragma unroll
        for (int g = 0; g < 2; g++) {
            uint32_t a = bRB[g] + soff + (uint32_t)((khB ^ bR3[g]) << 4);
            ldm_x4(bh[0][g], a);
            ldm_x4(bl[0][g], a + 16384);
        }

        #pragma unroll
        for (int s = 0; s < 4; s++) {
            int cur = s & 1, nxt = cur ^ 1;
            if (s < 3) {   // prefetch slab s+1 frags while computing slab s
                #pragma unroll
                for (int mt = 0; mt < 4; mt++) {
                    uint32_t a = aRB[mt] + soff + (uint32_t)((((s + 1) * 2 + khA) ^ aR3[mt]) << 4);
                    ldm_x4(ah[nxt][mt], a);
                    ldm_x4(al[nxt][mt], a + 16384);
                }
                #pragma unroll
                for (int g = 0; g < 2; g++) {
                    uint32_t a = bRB[g] + soff + (uint32_t)((((s + 1) * 2 + khB) ^ bR3[g]) << 4);
                    ldm_x4(bh[nxt][g], a);
                    ldm_x4(bl[nxt][g], a + 16384);
                }
            }
            #pragma unroll
            for (int mt = 0; mt < 4; mt++)
                #pragma unroll
                for (int nt = 0; nt < 4; nt++)
                    MMA(acc[mt][nt], ah[cur][mt], bh[cur][nt >> 1][(nt & 1) * 2], bh[cur][nt >> 1][(nt & 1) * 2 + 1]);
            #pragma unroll
            for (int mt = 0; mt < 4; mt++)
                #pragma unroll
                for (int nt = 0; nt < 4; nt++)
                    MMA(acc[mt][nt], ah[cur][mt], bl[cur][nt >> 1][(nt & 1) * 2], bl[cur][nt >> 1][(nt & 1) * 2 + 1]);
            #pragma unroll
            for (int mt = 0; mt < 4; mt++)
                #pragma unroll
                for (int nt = 0; nt < 4; nt++)
                    MMA(acc[mt][nt], al[cur][mt], bh[cur][nt >> 1][(nt & 1) * 2], bh[cur][nt >> 1][(nt & 1) * 2 + 1]);
        }
    }

    // epilogue
    const bool qkv_act = (EPI == 3) && (bn0 < 2 * DMODEL);
    #pragma unroll
    for (int mt = 0; mt < 4; mt++) {
        #pragma unroll
        for (int nt = 0; nt < 4; nt++) {
            int row = bm0 + wm * 64 + mt * 16 + (lane >> 2);
            int col = bn0 + wn * 32 + nt * 8 + (lane & 3) * 2;
            float* a = acc[mt][nt];
            #pragma unroll
            for (int half = 0; half < 2; half++) {
                int r = row + half * 8;
                float v0 = a[half * 2], v1 = a[half * 2 + 1];
                size_t o = (size_t)r * Ndim + col;
                if (EPI == 0) {
                    float2 t = {v0, v1};
                    *(float2*)(Cf + o) = t;
                } else if (EPI == 3) {
                    float2 t;
                    if (qkv_act) {
                        t.x = v0 > 0.f ? v0 + 1.f : expf(v0);
                        t.y = v1 > 0.f ? v1 + 1.f : expf(v1);
                    } else { t.x = v0; t.y = v1; }
                    *(float2*)(Cf + o) = t;
                } else {
                    v0 = v0 > 0.f ? v0 : 0.f;
                    v1 = v1 > 0.f ? v1 : 0.f;
                    __nv_bfloat16 h0, l0, h1, l1;
                    split2(v0, h0, l0); split2(v1, h1, l1);
                    __nv_bfloat162 ph; ph.x = h0; ph.y = h1;
                    __nv_bfloat162 pl; pl.x = l0; pl.y = l1;
                    *(__nv_bfloat162*)(Ch + o) = ph;
                    *(__nv_bfloat162*)(Cl + o) = pl;
                }
            }
        }
    }
}

// ---------------- KV reduce (two-phase, 32-row tiles) ----------------
__global__ __launch_bounds__(256) void kv_reduce1() {
    int blk = blockIdx.x;
    int sl = blk & 7, nh = blk >> 3;
    int n = nh >> 3, h = nh & 7;
    const float* Kp = g_qkv + (size_t)n * LSEQ * QKVN + DMODEL + h * DHEAD;
    const float* Vp = Kp + DMODEL;
    __shared__ float sK[32][32], sV[32][32];
    int tid = threadIdx.x;
    int d0 = tid >> 3, v0 = (tid & 7) * 4;
    int lrow = tid >> 3, lcol = (tid & 7) * 4;
    float a0 = 0, a1 = 0, a2 = 0, a3 = 0, ks = 0;
    int lbeg = sl * 512, lend = lbeg + 512;
    for (int l0 = lbeg; l0 < lend; l0 += 32) {
        size_t ro = (size_t)(l0 + lrow) * QKVN + lcol;
        *(float4*)&sK[lrow][lcol] = *(const float4*)(Kp + ro);
        *(float4*)&sV[lrow][lcol] = *(const float4*)(Vp + ro);
        __syncthreads();
        #pragma unroll
        for (int r = 0; r < 32; r++) {
            float kd = sK[r][d0];
            a0 += kd * sV[r][v0 + 0];
            a1 += kd * sV[r][v0 + 1];
            a2 += kd * sV[r][v0 + 2];
            a3 += kd * sV[r][v0 + 3];
            if ((tid & 7) == 0) ks += kd;
        }
        __syncthreads();
    }
    float* p = g_kvp + (size_t)blk * (DHEAD * DHEAD + DHEAD);
    float* kv = p + d0 * DHEAD + v0;
    kv[0] = a0; kv[1] = a1; kv[2] = a2; kv[3] = a3;
    if ((tid & 7) == 0) p[DHEAD * DHEAD + d0] = ks;
}
__global__ __launch_bounds__(256) void kv_reduce2() {
    int nh = blockIdx.x, tid = threadIdx.x;
    const float* base = g_kvp + (size_t)nh * 8 * (DHEAD * DHEAD + DHEAD);
    #pragma unroll
    for (int ii = 0; ii < 4; ii++) {
        int i = ii * 256 + tid;
        float s = 0;
        #pragma unroll
        for (int p = 0; p < 8; p++) s += base[p * (DHEAD * DHEAD + DHEAD) + i];
        g_kv[(size_t)nh * DHEAD * DHEAD + i] = s;
    }
    if (tid < DHEAD) {
        float s = 0;
        #pragma unroll
        for (int p = 0; p < 8; p++) s += base[p * (DHEAD * DHEAD + DHEAD) + DHEAD * DHEAD + tid];
        g_ksum[(size_t)nh * DHEAD + tid] = s;
    }
}

// ---------------- attention apply ----------------
__global__ __launch_bounds__(256) void attn_apply() {
    int n = blockIdx.y, l0 = blockIdx.x * 128;
    __shared__ float sKV[NHEAD][DHEAD][DHEAD];
    __shared__ float sKs[NHEAD][DHEAD];
    int tid = threadIdx.x;
    const float* kvp = g_kv + (size_t)n * NHEAD * DHEAD * DHEAD;
    for (int i = tid; i < NHEAD * DHEAD * DHEAD; i += 256) ((float*)sKV)[i] = kvp[i];
    for (int i = tid; i < NHEAD * DHEAD; i += 256) ((float*)sKs)[i] = g_ksum[(size_t)n * NHEAD * DHEAD + i];
    __syncthreads();
    #pragma unroll
    for (int p = 0; p < 4; p++) {
        int i = p * 256 + tid;
        int h = i >> 7, ll = i & 127;
        const float* qp = g_qkv + ((size_t)n * LSEQ + l0 + ll) * QKVN + h * DHEAD;
        size_t rowo = ((size_t)n * LSEQ + l0 + ll) * DMODEL + h * DHEAD;
        float q[32];
        #pragma unroll
        for (int d = 0; d < 32; d += 4) {
            float4 t = *(const float4*)(qp + d);
            q[d] = t.x; q[d + 1] = t.y; q[d + 2] = t.z; q[d + 3] = t.w;
        }
        float zdot = 0.f;
        #pragma unroll
        for (int d = 0; d < 32; d++) zdot += q[d] * sKs[h][d];
        float z = 1.f / (zdot + 1e-6f);
        #pragma unroll
        for (int v = 0; v < 32; v += 2) {
            float b0 = 0.f, b1 = 0.f;
            #pragma unroll
            for (int d = 0; d < 32; d++) {
                float qq = q[d];
                b0 += qq * sKV[h][d][v];
                b1 += qq * sKV[h][d][v + 1];
            }
            b0 *= z; b1 *= z;
            __nv_bfloat16 h0, l0b, h1, l1b;
            split2(b0, h0, l0b); split2(b1, h1, l1b);
            __nv_bfloat162 ph; ph.x = h0; ph.y = h1;
            __nv_bfloat162 pl; pl.x = l0b; pl.y = l1b;
            *(__nv_bfloat162*)(g_msgh + rowo + v) = ph;
            *(__nv_bfloat162*)(g_msgl + rowo + v) = pl;
        }
    }
}

// ---------------- LayerNorms ----------------
__device__ __forceinline__ float warp_sum(float v) {
    #pragma unroll
    for (int o = 16; o > 0; o >>= 1) v += __shfl_xor_sync(0xffffffffu, v, o);
    return v;
}
// LN1: write split(LN(merged)) to g_lnh/g_lnl (x half is reused from g_xh/g_xl)
__global__ __launch_bounds__(256) void ln1(
    const float* __restrict__ inp, const float* __restrict__ gam, const float* __restrict__ bet)
{
    int row = blockIdx.x * 8 + (threadIdx.x >> 5);
    int lane = threadIdx.x & 31;
    const float* ip = inp + (size_t)row * DMODEL;
    float v[8]; float s = 0.f;
    #pragma unroll
    for (int j = 0; j < 8; j++) { v[j] = ip[lane + 32 * j]; s += v[j]; }
    s = warp_sum(s);
    float mu = s * (1.f / 256.f), s2 = 0.f;
    #pragma unroll
    for (int j = 0; j < 8; j++) { float d = v[j] - mu; s2 += d * d; }
    s2 = warp_sum(s2);
    float rs = rsqrtf(s2 * (1.f / 256.f) + 1e-5f);
    size_t co = (size_t)row * DMODEL;
    #pragma unroll
    for (int j = 0; j < 8; j++) {
        int c = lane + 32 * j;
        float lnv = (v[j] - mu) * rs * gam[c] + bet[c];
        __nv_bfloat16 h, l; split2(lnv, h, l);
        g_lnh[co + c] = h; g_lnl[co + c] = l;
    }
}
__global__ __launch_bounds__(256) void ln2_res(
    const float* __restrict__ inp, const float* __restrict__ gam, const float* __restrict__ bet)
{
    int row = blockIdx.x * 8 + (threadIdx.x >> 5);
    int lane = threadIdx.x & 31;
    const float* ip = inp + (size_t)row * DMODEL;
    float v[8]; float s = 0.f;
    #pragma unroll
    for (int j = 0; j < 8; j++) { v[j] = ip[lane + 32 * j]; s += v[j]; }
    s = warp_sum(s);
    float mu = s * (1.f / 256.f), s2 = 0.f;
    #pragma unroll
    for (int j = 0; j < 8; j++) { float d = v[j] - mu; s2 += d * d; }
    s2 = warp_sum(s2);
    float rs = rsqrtf(s2 * (1.f / 256.f) + 1e-5f);
    float* xp = g_x + (size_t)row * DMODEL;
    size_t xo = (size_t)row * DMODEL;
    #pragma unroll
    for (int j = 0; j < 8; j++) {
        int c = lane + 32 * j;
        float nx = xp[c] + (v[j] - mu) * rs * gam[c] + bet[c];
        xp[c] = nx;
        __nv_bfloat16 h, l; split2(nx, h, l);
        g_xh[xo + c] = h; g_xl[xo + c] = l;
    }
}

// ---------------- host ----------------
extern "C" void kernel_launch(void* const* d_in, const int* in_sizes, int n_in,
                              void* d_out, int out_size)
{
    const float* feats = (const float*)d_in[0];
    const float* Wq = (const float*)d_in[1];
    const float* Wk = (const float*)d_in[2];
    const float* Wv = (const float*)d_in[3];
    const float* Wm = (const float*)d_in[4];
    const float* W1 = (const float*)d_in[5];
    const float* W2 = (const float*)d_in[6];
    const float* ln1g = (const float*)d_in[7];
    const float* ln1b = (const float*)d_in[8];
    const float* ln2g = (const float*)d_in[9];
    const float* ln2b = (const float*)d_in[10];

    cudaFuncSetAttribute(mmagemm<0, false>, cudaFuncAttributeMaxDynamicSharedMemorySize, GSMEM);
    cudaFuncSetAttribute(mmagemm<2, true>,  cudaFuncAttributeMaxDynamicSharedMemorySize, GSMEM);
    cudaFuncSetAttribute(mmagemm<3, false>, cudaFuncAttributeMaxDynamicSharedMemorySize, GSMEM);

    float *px, *pqkv, *ptmp;
    __nv_bfloat16 *pxh, *pxl, *pmh, *pml, *plh, *pll, *p1h, *p1l, *pwh, *pwl;
    cudaGetSymbolAddress((void**)&px, g_x);
    cudaGetSymbolAddress((void**)&pqkv, g_qkv);
    cudaGetSymbolAddress((void**)&ptmp, g_tmp);
    cudaGetSymbolAddress((void**)&pxh, g_xh);
    cudaGetSymbolAddress((void**)&pxl, g_xl);
    cudaGetSymbolAddress((void**)&pmh, g_msgh);
    cudaGetSymbolAddress((void**)&pml, g_msgl);
    cudaGetSymbolAddress((void**)&plh, g_lnh);
    cudaGetSymbolAddress((void**)&pll, g_lnl);
    cudaGetSymbolAddress((void**)&p1h, g_h1h);
    cudaGetSymbolAddress((void**)&p1l, g_h1l);
    cudaGetSymbolAddress((void**)&pwh, g_wh);
    cudaGetSymbolAddress((void**)&pwl, g_wl);

    dim3 tb(32, 8);
    prep_weight<<<dim3(8, 8, NUM_LAYERS), tb>>>(Wq, pwh + OFF_Q, pwl + OFF_Q, DMODEL, DMODEL, WSZ_D, WSZ_L);
    prep_weight<<<dim3(8, 8, NUM_LAYERS), tb>>>(Wk, pwh + OFF_K, pwl + OFF_K, DMODEL, DMODEL, WSZ_D, WSZ_L);
    prep_weight<<<dim3(8, 8, NUM_LAYERS), tb>>>(Wv, pwh + OFF_V, pwl + OFF_V, DMODEL, DMODEL, WSZ_D, WSZ_L);
    prep_weight<<<dim3(8, 8, NUM_LAYERS), tb>>>(Wm, pwh + OFF_M, pwl + OFF_M, DMODEL, DMODEL, WSZ_D, WSZ_L);
    prep_weight<<<dim3(16, 16, NUM_LAYERS), tb>>>(W1, pwh + OFF_1, pwl + OFF_1, 2 * DMODEL, 2 * DMODEL, 4 * WSZ_D, WSZ_L);
    prep_weight<<<dim3(8, 16, NUM_LAYERS), tb>>>(W2, pwh + OFF_2, pwl + OFF_2, 2 * DMODEL, DMODEL, 2 * WSZ_D, WSZ_L);

    add_pe_transpose<<<dim3(LSEQ / 32, DMODEL / 32, BATCH), tb>>>(feats);

    dim3 blk(256);
    dim3 grid_qkv(QKVN / BN, MROWS / BM);       // (6, 256)
    dim3 grid_d(DMODEL / BN, MROWS / BM);       // (2, 256)
    dim3 grid_2d(2 * DMODEL / BN, MROWS / BM);  // (4, 256)

    for (int i = 0; i < NUM_LAYERS; i++) {
        size_t wo = (size_t)i * WSZ_L;
        // fused QKV: [elu(x@Wq)+1 | elu(x@Wk)+1 | x@Wv] -> g_qkv [M][768]
        mmagemm<3, false><<<grid_qkv, blk, GSMEM>>>(pxh, pxl, 0, 0, pwh + wo + OFF_Q, pwl + wo + OFF_Q, pqkv, 0, 0, QKVN, DMODEL);

        kv_reduce1<<<BATCH * NHEAD * 8, 256>>>();
        kv_reduce2<<<BATCH * NHEAD, 256>>>();
        attn_apply<<<dim3(LSEQ / 128, BATCH), 256>>>();

        // merged = msg @ Wm -> g_tmp fp32
        mmagemm<0, false><<<grid_d, blk, GSMEM>>>(pmh, pml, 0, 0, pwh + wo + OFF_M, pwl + wo + OFF_M, ptmp, 0, 0, DMODEL, DMODEL);
        ln1<<<MROWS / 8, 256>>>(ptmp, ln1g + i * DMODEL, ln1b + i * DMODEL);

        // h1 = relu([x | LN] @ W1) -> split; h2 = h1 @ W2 -> g_tmp fp32
        mmagemm<2, true><<<grid_2d, blk, GSMEM>>>(pxh, pxl, plh, pll, pwh + wo + OFF_1, pwl + wo + OFF_1, 0, p1h, p1l, 2 * DMODEL, 2 * DMODEL);
        mmagemm<0, false><<<grid_d, blk, GSMEM>>>(p1h, p1l, 0, 0, pwh + wo + OFF_2, pwl + wo + OFF_2, ptmp, 0, 0, DMODEL, 2 * DMODEL);

        ln2_res<<<MROWS / 8, 256>>>(ptmp, ln2g + i * DMODEL, ln2b + i * DMODEL);
    }

    transpose_out<<<dim3(LSEQ / 32, DMODEL / 32, BATCH), tb>>>((float*)d_out);
}